// round 10
// baseline (speedup 1.0000x reference)
#include <cuda_runtime.h>
#include <math.h>
#include <mma.h>

// ---------------------------------------------------------------------------
// SimGNN on GB300: two GCN stacks in two concurrent streams; GEMMs on TF32
// tensor cores (wmma m16n16k8) -> attention pooling -> NTN -> MLP
// ---------------------------------------------------------------------------

#define MAXN 100000
#define MAXE 1300000
#define XCAP ((size_t)MAXN * 128)

using namespace nvcuda;

// Scratch, doubled so the two graph pipelines never alias
__device__ __align__(16) float g_bufA[2 * XCAP];
__device__ __align__(16) float g_bufB[2 * XCAP];
__device__ __align__(16) float g_bufC[2 * XCAP];
__device__ __align__(16) float g_dinv[2 * MAXN];
__device__ __align__(16) int   g_deg [2 * MAXN];
__device__ __align__(16) int   g_off [2 * (MAXN + 1)];
__device__ __align__(16) int   g_cur [2 * MAXN];
__device__ __align__(16) int   g_part[2 * 256];
__device__ __align__(16) int2  g_csr [2 * (size_t)MAXE];
__device__ __align__(16) float g_colsum[2 * 64];
__device__ __align__(16) float g_gc[2 * 64];
__device__ __align__(16) float g_h[128];

// Streams/events created once at static-init (no device-memory API).
static cudaStream_t g_s2;
static cudaEvent_t  g_evFork, g_evJoin;
namespace {
struct StreamInit {
    StreamInit() {
        cudaStreamCreateWithFlags(&g_s2, cudaStreamNonBlocking);
        cudaEventCreateWithFlags(&g_evFork, cudaEventDisableTiming);
        cudaEventCreateWithFlags(&g_evJoin, cudaEventDisableTiming);
    }
};
static StreamInit s_streamInit;
}

// ---------------------------------------------------------------------------
__global__ void zero_all_kernel(int* __restrict__ deg, float* __restrict__ h,
                                float* __restrict__ colsum, int n2)
{
    int i = blockIdx.x * blockDim.x + threadIdx.x;
    if (i < n2) deg[i] = 0;
    if (i < 128) { h[i] = 0.f; colsum[i] = 0.f; }
}

__global__ void deg_kernel(const int* __restrict__ dst, int* __restrict__ deg, int E) {
    int i = blockIdx.x * blockDim.x + threadIdx.x;
    if (i < E) atomicAdd(&deg[dst[i]], 1);
}

// --------------------------- CSR build: scan ------------------------------
__global__ void scan1_kernel(const int* __restrict__ deg, int* __restrict__ off,
                             int* __restrict__ partials, int n)
{
    __shared__ int wsum[32];
    int gid  = blockIdx.x * 1024 + threadIdx.x;
    int lane = threadIdx.x & 31, wid = threadIdx.x >> 5;
    int v = (gid < n) ? deg[gid] : 0;
    int x = v;
#pragma unroll
    for (int o = 1; o < 32; o <<= 1) {
        int y = __shfl_up_sync(0xFFFFFFFFu, x, o);
        if (lane >= o) x += y;
    }
    if (lane == 31) wsum[wid] = x;
    __syncthreads();
    if (wid == 0) {
        int s = wsum[lane];
#pragma unroll
        for (int o = 1; o < 32; o <<= 1) {
            int y = __shfl_up_sync(0xFFFFFFFFu, s, o);
            if (lane >= o) s += y;
        }
        wsum[lane] = s;
    }
    __syncthreads();
    int excl = (wid > 0 ? wsum[wid - 1] : 0) + x - v;
    if (gid < n) off[gid] = excl;
    if (threadIdx.x == 1023) partials[blockIdx.x] = wsum[31];
}

__global__ void scan2_kernel(int* __restrict__ partials, int nb)
{
    __shared__ int wsum[4];
    int t = threadIdx.x;                 // 128 threads
    int lane = t & 31, w = t >> 5;
    int v = (t < nb) ? partials[t] : 0;
    int x = v;
#pragma unroll
    for (int o = 1; o < 32; o <<= 1) {
        int y = __shfl_up_sync(0xFFFFFFFFu, x, o);
        if (lane >= o) x += y;
    }
    if (lane == 31) wsum[w] = x;
    __syncthreads();
    if (w == 0 && lane < 4) {
        int s = wsum[lane];
#pragma unroll
        for (int o = 1; o < 4; o <<= 1) {
            int y = __shfl_up_sync(0x0000000Fu, s, o);
            if (lane >= o) s += y;
        }
        wsum[lane] = s;
    }
    __syncthreads();
    int incl = x + (w > 0 ? wsum[w - 1] : 0);
    if (t < nb) partials[t] = incl - v;
}

__global__ void scan3_kernel(int* __restrict__ off, const int* __restrict__ partials,
                             int* __restrict__ cur, const int* __restrict__ deg,
                             float* __restrict__ dinv, int n)
{
    int gid = blockIdx.x * blockDim.x + threadIdx.x;
    if (gid < n) {
        int o = off[gid] + partials[gid >> 10];
        off[gid] = o;
        cur[gid] = o;
        if (gid == n - 1) off[n] = o + deg[gid];
        dinv[gid] = rsqrtf((float)(deg[gid] + 1));   // +1 self loop
    }
}

__global__ void scatter_kernel(const int* __restrict__ src, const int* __restrict__ dst,
                               const float* __restrict__ dinv, int* __restrict__ cur,
                               int2* __restrict__ csr, int E)
{
    int e = blockIdx.x * blockDim.x + threadIdx.x;
    if (e >= E) return;
    int s = src[e], d = dst[e];
    int pos = atomicAdd(&cur[d], 1);
    csr[pos] = make_int2(s, __float_as_int(__ldg(&dinv[s])));
}

// ---------------------------------------------------------------------------
// TF32 tensor-core GEMM: xw = relu_fused(in) @ W.
// Block: 64 rows x DOUT cols, 256 threads (8 warps). Warp w handles row-tile
// rt = w/2 (16 rows) and NT = DOUT/32 col-tiles starting at (w&1)*NT.
// fp32 accumulate; fused bias+relu on the x-tile load.
template<int DIN, int DOUT, bool FUSE>
__global__ void __launch_bounds__(256)
gemm_tc_kernel(const float* __restrict__ in, const float* __restrict__ W,
               const float* __restrict__ bprev, float* __restrict__ xw, int n)
{
    constexpr int WS = DOUT + 4;     // padded W row stride (floats)
    constexpr int XS = DIN + 4;      // padded x row stride (floats)
    constexpr int CT = DOUT / 16;    // col tiles
    constexpr int NT = CT / 2;       // col tiles per warp (4 or 2)

    extern __shared__ float sh[];
    float* Ws    = sh;                        // DIN * WS
    float* xs    = sh + DIN * WS;             // 64 * XS
    float* stage = xs + 64 * XS;              // 8 * 256 (tail staging)

    const int tid  = threadIdx.x;
    const int w    = tid >> 5;
    const int lane = tid & 31;

    // Load W into smem (padded rows)
    for (int i = tid; i < DIN * DOUT / 4; i += 256) {
        int row = i / (DOUT / 4), c4 = i % (DOUT / 4);
        ((float4*)(Ws + row * WS))[c4] = ((const float4*)(W + row * DOUT))[c4];
    }

    // Load x tile (64 rows) with fused bias+relu, zero-pad OOB rows
    const int row0 = blockIdx.x * 64;
    for (int i = tid; i < 64 * DIN / 4; i += 256) {
        int r = i / (DIN / 4), kk = i % (DIN / 4);
        int row = row0 + r;
        float4 v = make_float4(0.f, 0.f, 0.f, 0.f);
        if (row < n) {
            v = ((const float4*)(in + (size_t)row * DIN))[kk];
            if (FUSE) {
                float4 b = ((const float4*)bprev)[kk];
                v.x = fmaxf(v.x + b.x, 0.f);
                v.y = fmaxf(v.y + b.y, 0.f);
                v.z = fmaxf(v.z + b.z, 0.f);
                v.w = fmaxf(v.w + b.w, 0.f);
            }
        }
        ((float4*)(xs + r * XS))[kk] = v;
    }
    __syncthreads();

    const int rt  = w >> 1;                 // row tile 0..3
    const int ctb = (w & 1) * NT;           // first col tile

    wmma::fragment<wmma::accumulator, 16, 16, 8, float> acc[NT];
#pragma unroll
    for (int t = 0; t < NT; t++) wmma::fill_fragment(acc[t], 0.f);

#pragma unroll
    for (int k0 = 0; k0 < DIN; k0 += 8) {
        wmma::fragment<wmma::matrix_a, 16, 16, 8, wmma::precision::tf32, wmma::row_major> a;
        wmma::load_matrix_sync(a, xs + rt * 16 * XS + k0, XS);
#pragma unroll
        for (int i = 0; i < a.num_elements; i++)
            a.x[i] = wmma::__float_to_tf32(a.x[i]);
#pragma unroll
        for (int t = 0; t < NT; t++) {
            wmma::fragment<wmma::matrix_b, 16, 16, 8, wmma::precision::tf32, wmma::row_major> b;
            wmma::load_matrix_sync(b, Ws + k0 * WS + (ctb + t) * 16, WS);
#pragma unroll
            for (int i = 0; i < b.num_elements; i++)
                b.x[i] = wmma::__float_to_tf32(b.x[i]);
            wmma::mma_sync(acc[t], a, b, acc[t]);
        }
    }

    const int trow = row0 + rt * 16;
    if (trow + 16 <= n) {
        // full tile: direct global store
#pragma unroll
        for (int t = 0; t < NT; t++)
            wmma::store_matrix_sync(xw + (size_t)trow * DOUT + (ctb + t) * 16,
                                    acc[t], DOUT, wmma::mem_row_major);
    } else if (trow < n) {
        // partial tile: stage in smem, guarded copy
        float* st = stage + w * 256;
#pragma unroll
        for (int t = 0; t < NT; t++) {
            wmma::store_matrix_sync(st, acc[t], 16, wmma::mem_row_major);
            __syncwarp();
            for (int idx = lane; idx < 256; idx += 32) {
                int r = idx >> 4, c = idx & 15;
                if (trow + r < n)
                    xw[(size_t)(trow + r) * DOUT + (ctb + t) * 16 + c] = st[idx];
            }
            __syncwarp();
        }
    }
}

// ---------------------------------------------------------------------------
// CSR aggregation: out[d] = feat[d]*dinv[d]^2 + sum_in dinv[s]*dinv[d]*feat[s].
template<int DOUT>
__global__ void agg_csr_kernel(const int* __restrict__ off, const int2* __restrict__ csr,
                               const float* __restrict__ xw, const float* __restrict__ dinv,
                               float* __restrict__ aggout, int n)
{
    constexpr int VEC = DOUT / 32;   // 4 or 2
    int node = blockIdx.x * 8 + (threadIdx.x >> 5);
    if (node >= n) return;
    int lane = threadIdx.x & 31;

    float dv = __ldg(&dinv[node]);
    const float* xr = xw + (size_t)node * DOUT + lane * VEC;
    float acc[VEC], acc2[VEC];
    if (VEC == 4) {
        float4 v = *(const float4*)xr;
        acc[0] = v.x * dv * dv; acc[1] = v.y * dv * dv;
        acc[2] = v.z * dv * dv; acc[3] = v.w * dv * dv;
        acc2[0] = acc2[1] = acc2[2] = acc2[3] = 0.f;
    } else {
        float2 v = *(const float2*)xr;
        acc[0] = v.x * dv * dv; acc[1] = v.y * dv * dv;
        acc2[0] = acc2[1] = 0.f;
    }

    int p = __ldg(&off[node]);
    int pend = __ldg(&off[node + 1]);
    for (; p + 2 <= pend; p += 2) {
        int2 e0 = __ldg(&csr[p]);
        int2 e1 = __ldg(&csr[p + 1]);
        float n0 = __int_as_float(e0.y) * dv;
        float n1 = __int_as_float(e1.y) * dv;
        const float* s0 = xw + (size_t)e0.x * DOUT + lane * VEC;
        const float* s1 = xw + (size_t)e1.x * DOUT + lane * VEC;
        if (VEC == 4) {
            float4 v0 = *(const float4*)s0;
            float4 v1 = *(const float4*)s1;
            acc[0] = fmaf(n0, v0.x, acc[0]); acc[1] = fmaf(n0, v0.y, acc[1]);
            acc[2] = fmaf(n0, v0.z, acc[2]); acc[3] = fmaf(n0, v0.w, acc[3]);
            acc2[0] = fmaf(n1, v1.x, acc2[0]); acc2[1] = fmaf(n1, v1.y, acc2[1]);
            acc2[2] = fmaf(n1, v1.z, acc2[2]); acc2[3] = fmaf(n1, v1.w, acc2[3]);
        } else {
            float2 v0 = *(const float2*)s0;
            float2 v1 = *(const float2*)s1;
            acc[0] = fmaf(n0, v0.x, acc[0]); acc[1] = fmaf(n0, v0.y, acc[1]);
            acc2[0] = fmaf(n1, v1.x, acc2[0]); acc2[1] = fmaf(n1, v1.y, acc2[1]);
        }
    }
    if (p < pend) {
        int2 e0 = __ldg(&csr[p]);
        float n0 = __int_as_float(e0.y) * dv;
        const float* s0 = xw + (size_t)e0.x * DOUT + lane * VEC;
        if (VEC == 4) {
            float4 v0 = *(const float4*)s0;
            acc[0] = fmaf(n0, v0.x, acc[0]); acc[1] = fmaf(n0, v0.y, acc[1]);
            acc[2] = fmaf(n0, v0.z, acc[2]); acc[3] = fmaf(n0, v0.w, acc[3]);
        } else {
            float2 v0 = *(const float2*)s0;
            acc[0] = fmaf(n0, v0.x, acc[0]); acc[1] = fmaf(n0, v0.y, acc[1]);
        }
    }

    float* o = aggout + (size_t)node * DOUT + lane * VEC;
    if (VEC == 4)
        *(float4*)o = make_float4(acc[0] + acc2[0], acc[1] + acc2[1],
                                  acc[2] + acc2[2], acc[3] + acc2[3]);
    else
        *(float2*)o = make_float2(acc[0] + acc2[0], acc[1] + acc2[1]);
}

// ---------------------------------------------------------------------------
__global__ void colsum_kernel(const float* __restrict__ agg, float* __restrict__ colsum, int n)
{
    __shared__ float sm[256];
    int c  = threadIdx.x & 63;
    int rl = threadIdx.x >> 6;
    float acc = 0.f;
    for (int row = blockIdx.x * 4 + rl; row < n; row += gridDim.x * 4)
        acc += agg[(size_t)row * 64 + c];
    sm[threadIdx.x] = acc;
    __syncthreads();
    if (threadIdx.x < 64) {
        float s = sm[c] + sm[64 + c] + sm[128 + c] + sm[192 + c];
        atomicAdd(&colsum[c], s);
    }
}

__global__ void gc_kernel(const float* __restrict__ colsum, const float* __restrict__ b2,
                          const float* __restrict__ Wa, float* __restrict__ gc, float invN)
{
    __shared__ float mean[64];
    int t = threadIdx.x;
    mean[t] = colsum[t] * invN + b2[t];
    __syncthreads();
    float acc = 0.f;
#pragma unroll
    for (int d = 0; d < 64; d++) acc += mean[d] * Wa[d * 64 + t];
    gc[t] = tanhf(acc);
}

__global__ void attpool_kernel(const float* __restrict__ agg, const float* __restrict__ b2,
                               const float* __restrict__ gc, float* __restrict__ h, int n)
{
    __shared__ float gcs[64], b2s[64];
    __shared__ float red[8][64];
    int tid = threadIdx.x;
    if (tid < 64) { gcs[tid] = gc[tid]; b2s[tid] = b2[tid]; }
    __syncthreads();
    int lane = tid & 31, w = tid >> 5;
    float gx = gcs[2 * lane], gy = gcs[2 * lane + 1];
    float bx = b2s[2 * lane], by = b2s[2 * lane + 1];
    float ax = 0.f, ay = 0.f;
    for (int row = blockIdx.x * 8 + w; row < n; row += gridDim.x * 8) {
        float2 v = *(const float2*)(agg + (size_t)row * 64 + 2 * lane);
        v.x += bx; v.y += by;
        float d = v.x * gx + v.y * gy;
#pragma unroll
        for (int o = 16; o; o >>= 1) d += __shfl_xor_sync(0xFFFFFFFFu, d, o);
        float att = 1.f / (1.f + expf(-d));
        ax += v.x * att; ay += v.y * att;
    }
    red[w][2 * lane] = ax; red[w][2 * lane + 1] = ay;
    __syncthreads();
    if (w == 0) {
        float sx = 0.f, sy = 0.f;
#pragma unroll
        for (int i = 0; i < 8; i++) { sx += red[i][2 * lane]; sy += red[i][2 * lane + 1]; }
        atomicAdd(&h[2 * lane], sx);
        atomicAdd(&h[2 * lane + 1], sy);
    }
}

// ---------------------------------------------------------------------------
__global__ void final_kernel(const float* __restrict__ h,
                             const float* __restrict__ Wt, const float* __restrict__ Wm,
                             const float* __restrict__ nb,
                             const float* __restrict__ w0, const float* __restrict__ bb0,
                             const float* __restrict__ w1, const float* __restrict__ bb1,
                             const float* __restrict__ w2, const float* __restrict__ bb2,
                             const float* __restrict__ w3, const float* __restrict__ bb3,
                             const float* __restrict__ sw, const float* __restrict__ sb,
                             float* __restrict__ out)
{
    __shared__ float hi[64], hj[64];
    __shared__ float part[1024];
    __shared__ float z[16];
    int t = threadIdx.x;
    if (t < 64) hi[t] = h[t];
    else if (t < 128) hj[t - 64] = h[t];
    __syncthreads();

    int k = t >> 6, e = t & 63;
    const float* wt = Wt + (size_t)k * 4096 + e;
    float acc = 0.f;
#pragma unroll
    for (int d = 0; d < 64; d++) acc += hi[d] * wt[d * 64];
    part[t] = acc * hj[e];
    __syncthreads();

    if (t < 16) {
        float s = 0.f;
        for (int e2 = 0; e2 < 64; e2++) s += part[t * 64 + e2];
        float lin = 0.f;
        const float* wm = Wm + t * 128;
        for (int m = 0; m < 64; m++) lin += wm[m] * hi[m] + wm[64 + m] * hj[m];
        z[t] = tanhf(s + lin + nb[t]);
    }
    __syncthreads();

    if (t == 0) {
        float a[32], b[32];
        for (int j = 0; j < 32; j++) { float s = bb0[j]; for (int i = 0; i < 16; i++) s += z[i] * w0[i * 32 + j]; a[j] = fmaxf(s, 0.f); }
        for (int j = 0; j < 16; j++) { float s = bb1[j]; for (int i = 0; i < 32; i++) s += a[i] * w1[i * 16 + j]; b[j] = fmaxf(s, 0.f); }
        for (int j = 0; j <  8; j++) { float s = bb2[j]; for (int i = 0; i < 16; i++) s += b[i] * w2[i * 8 + j];  a[j] = fmaxf(s, 0.f); }
        for (int j = 0; j <  4; j++) { float s = bb3[j]; for (int i = 0; i <  8; i++) s += a[i] * w3[i * 4 + j];  b[j] = fmaxf(s, 0.f); }
        float s = sb[0];
        for (int i = 0; i < 4; i++) s += b[i] * sw[i];
        out[0] = s;
    }
}

// ---------------------------------------------------------------------------
extern "C" void kernel_launch(void* const* d_in, const int* in_sizes, int n_in,
                              void* d_out, int out_size)
{
    const float* x_i = (const float*)d_in[0];
    const int*   ei  = (const int*)d_in[1];     // int32 (JAX x64 disabled)
    const float* x_j = (const float*)d_in[2];
    const int*   ej  = (const int*)d_in[3];
    const float* w0 = (const float*)d_in[4];
    const float* b0 = (const float*)d_in[5];
    const float* w1 = (const float*)d_in[6];
    const float* b1 = (const float*)d_in[7];
    const float* w2 = (const float*)d_in[8];
    const float* b2 = (const float*)d_in[9];
    const float* att_w  = (const float*)d_in[10];
    const float* ntn_wt = (const float*)d_in[11];
    const float* ntn_wm = (const float*)d_in[12];
    const float* ntn_b  = (const float*)d_in[13];
    const float* mw0 = (const float*)d_in[14];
    const float* mb0 = (const float*)d_in[15];
    const float* mw1 = (const float*)d_in[16];
    const float* mb1 = (const float*)d_in[17];
    const float* mw2 = (const float*)d_in[18];
    const float* mb2 = (const float*)d_in[19];
    const float* mw3 = (const float*)d_in[20];
    const float* mb3 = (const float*)d_in[21];
    const float* sw  = (const float*)d_in[22];
    const float* sb  = (const float*)d_in[23];
    float* out = (float*)d_out;

    const int N = in_sizes[0] / 64;
    const int E = in_sizes[1] / 2;

    float *bufA, *bufB, *bufC, *dinvp, *colsump, *gcp, *hp;
    int *degp, *offp, *curp, *partp;
    int2* csrp;
    cudaGetSymbolAddress((void**)&bufA,    g_bufA);
    cudaGetSymbolAddress((void**)&bufB,    g_bufB);
    cudaGetSymbolAddress((void**)&bufC,    g_bufC);
    cudaGetSymbolAddress((void**)&dinvp,   g_dinv);
    cudaGetSymbolAddress((void**)&degp,    g_deg);
    cudaGetSymbolAddress((void**)&offp,    g_off);
    cudaGetSymbolAddress((void**)&curp,    g_cur);
    cudaGetSymbolAddress((void**)&partp,   g_part);
    cudaGetSymbolAddress((void**)&csrp,    g_csr);
    cudaGetSymbolAddress((void**)&colsump, g_colsum);
    cudaGetSymbolAddress((void**)&gcp,     g_gc);
    cudaGetSymbolAddress((void**)&hp,      g_h);

    // smem: W(DIN*(DOUT+4)) + x(64*(DIN+4)) + stage(8*256), floats
    const int smem0 = (64  * 132 + 64 * 68  + 2048) * 4;   // 59392
    const int smem1 = (128 * 132 + 64 * 132 + 2048) * 4;   // 109568
    const int smem2 = (128 * 68  + 64 * 132 + 2048) * 4;   // 76800
    cudaFuncSetAttribute(gemm_tc_kernel<64, 128, false>, cudaFuncAttributeMaxDynamicSharedMemorySize, smem0);
    cudaFuncSetAttribute(gemm_tc_kernel<128, 128, true>, cudaFuncAttributeMaxDynamicSharedMemorySize, smem1);
    cudaFuncSetAttribute(gemm_tc_kernel<128, 64,  true>, cudaFuncAttributeMaxDynamicSharedMemorySize, smem2);

    const int gemm_blocks = (N + 63) / 64;
    const int agg_blocks  = (N + 7) / 8;
    const int scan_blocks = (N + 1023) / 1024;
    const int nb256 = (N + 255) / 256;
    const int eb256 = (E + 255) / 256;

    cudaStream_t s0 = 0;          // captured legacy stream
    cudaStream_t s1 = g_s2;       // forked stream

    zero_all_kernel<<<(2 * N + 255) / 256, 256, 0, s0>>>(degp, hp, colsump, 2 * N);
    cudaEventRecord(g_evFork, s0);
    cudaStreamWaitEvent(s1, g_evFork, 0);

    // ---------------- per-graph pipelines, concurrent ----------------
    for (int g = 0; g < 2; g++) {
        cudaStream_t st = g ? s1 : s0;
        const int* eidx = g ? ej : ei;
        const int* src  = eidx;
        const int* dst  = eidx + E;
        const float* x  = g ? x_j : x_i;
        int*   dg   = degp + g * MAXN;
        int*   off  = offp + g * (MAXN + 1);
        int*   cur  = curp + g * MAXN;
        int*   part = partp + g * 256;
        float* dnv  = dinvp + g * MAXN;
        int2*  csr  = csrp + (size_t)g * MAXE;
        float* bA = bufA + (size_t)g * XCAP;
        float* bB = bufB + (size_t)g * XCAP;
        float* bC = bufC + (size_t)g * XCAP;
        float* hout  = hp + g * 64;
        float* csumg = colsump + g * 64;
        float* gcg   = gcp + g * 64;

        // Layer-0 GEMM first (no CSR dependency): overlaps the other stream.
        gemm_tc_kernel<64, 128, false><<<gemm_blocks, 256, smem0, st>>>(x, w0, nullptr, bB, N);

        // CSR build
        deg_kernel<<<eb256, 256, 0, st>>>(dst, dg, E);
        scan1_kernel<<<scan_blocks, 1024, 0, st>>>(dg, off, part, N);
        scan2_kernel<<<1, 128, 0, st>>>(part, scan_blocks);
        scan3_kernel<<<nb256, 256, 0, st>>>(off, part, cur, dg, dnv, N);
        scatter_kernel<<<eb256, 256, 0, st>>>(src, dst, dnv, cur, csr, E);

        // Layer 0 aggregate (xW in bB)
        agg_csr_kernel<128><<<agg_blocks, 256, 0, st>>>(off, csr, bB, dnv, bA, N);
        // Layer 1
        gemm_tc_kernel<128, 128, true><<<gemm_blocks, 256, smem1, st>>>(bA, w1, b0, bC, N);
        agg_csr_kernel<128><<<agg_blocks, 256, 0, st>>>(off, csr, bC, dnv, bA, N);
        // Layer 2
        gemm_tc_kernel<128, 64, true><<<gemm_blocks, 256, smem2, st>>>(bA, w2, b1, bB, N);
        agg_csr_kernel<64><<<agg_blocks, 256, 0, st>>>(off, csr, bB, dnv, bC, N);

        // Attention pooling
        colsum_kernel<<<512, 256, 0, st>>>(bC, csumg, N);
        gc_kernel<<<1, 64, 0, st>>>(csumg, b2, att_w, gcg, 1.0f / (float)N);
        attpool_kernel<<<592, 256, 0, st>>>(bC, b2, gcg, hout, N);
    }

    cudaEventRecord(g_evJoin, s1);
    cudaStreamWaitEvent(s0, g_evJoin, 0);

    final_kernel<<<1, 1024, 0, s0>>>(hp, ntn_wt, ntn_wm, ntn_b,
                                     mw0, mb0, mw1, mb1, mw2, mb2, mw3, mb3,
                                     sw, sb, out);
}

// round 11
// speedup vs baseline: 1.1116x; 1.1116x over previous
#include <cuda_runtime.h>
#include <math.h>

// ---------------------------------------------------------------------------
// SimGNN on GB300: two GCN stacks in two concurrent streams, ANTI-PHASED
// (g0 GEMM-first, g1 CSR+aggregate-first) -> attention pooling -> NTN -> MLP
// ---------------------------------------------------------------------------

#define MAXN 100000
#define MAXE 1300000
#define XCAP ((size_t)MAXN * 128)

// Scratch, doubled so the two graph pipelines never alias
__device__ __align__(16) float g_bufA[2 * XCAP];
__device__ __align__(16) float g_bufB[2 * XCAP];
__device__ __align__(16) float g_bufC[2 * XCAP];
__device__ __align__(16) float g_dinv[2 * MAXN];
__device__ __align__(16) int   g_deg [2 * MAXN];
__device__ __align__(16) int   g_off [2 * (MAXN + 1)];
__device__ __align__(16) int   g_cur [2 * MAXN];
__device__ __align__(16) int   g_part[2 * 256];
__device__ __align__(16) int2  g_csr [2 * (size_t)MAXE];
__device__ __align__(16) float g_colsum[2 * 64];
__device__ __align__(16) float g_gc[2 * 64];
__device__ __align__(16) float g_h[128];   // [0:64)=h_i, [64:128)=h_j

// Streams/events created once at static-init (no device-memory API).
static cudaStream_t g_s2;
static cudaEvent_t  g_evFork, g_evJoin;
namespace {
struct StreamInit {
    StreamInit() {
        cudaStreamCreateWithFlags(&g_s2, cudaStreamNonBlocking);
        cudaEventCreateWithFlags(&g_evFork, cudaEventDisableTiming);
        cudaEventCreateWithFlags(&g_evJoin, cudaEventDisableTiming);
    }
};
static StreamInit s_streamInit;
}

// ---------------------------------------------------------------------------
__global__ void zero_all_kernel(int* __restrict__ deg, float* __restrict__ h,
                                float* __restrict__ colsum, int n2)
{
    int i = blockIdx.x * blockDim.x + threadIdx.x;
    if (i < n2) deg[i] = 0;
    if (i < 128) { h[i] = 0.f; colsum[i] = 0.f; }
}

__global__ void deg_kernel(const int* __restrict__ dst, int* __restrict__ deg, int E) {
    int i = blockIdx.x * blockDim.x + threadIdx.x;
    if (i < E) atomicAdd(&deg[dst[i]], 1);
}

// --------------------------- CSR build: scan ------------------------------
__global__ void scan1_kernel(const int* __restrict__ deg, int* __restrict__ off,
                             int* __restrict__ partials, int n)
{
    __shared__ int wsum[32];
    int gid  = blockIdx.x * 1024 + threadIdx.x;
    int lane = threadIdx.x & 31, wid = threadIdx.x >> 5;
    int v = (gid < n) ? deg[gid] : 0;
    int x = v;
#pragma unroll
    for (int o = 1; o < 32; o <<= 1) {
        int y = __shfl_up_sync(0xFFFFFFFFu, x, o);
        if (lane >= o) x += y;
    }
    if (lane == 31) wsum[wid] = x;
    __syncthreads();
    if (wid == 0) {
        int s = wsum[lane];
#pragma unroll
        for (int o = 1; o < 32; o <<= 1) {
            int y = __shfl_up_sync(0xFFFFFFFFu, s, o);
            if (lane >= o) s += y;
        }
        wsum[lane] = s;
    }
    __syncthreads();
    int excl = (wid > 0 ? wsum[wid - 1] : 0) + x - v;
    if (gid < n) off[gid] = excl;
    if (threadIdx.x == 1023) partials[blockIdx.x] = wsum[31];
}

__global__ void scan2_kernel(int* __restrict__ partials, int nb)
{
    __shared__ int wsum[4];
    int t = threadIdx.x;                 // 128 threads
    int lane = t & 31, w = t >> 5;
    int v = (t < nb) ? partials[t] : 0;
    int x = v;
#pragma unroll
    for (int o = 1; o < 32; o <<= 1) {
        int y = __shfl_up_sync(0xFFFFFFFFu, x, o);
        if (lane >= o) x += y;
    }
    if (lane == 31) wsum[w] = x;
    __syncthreads();
    if (w == 0 && lane < 4) {
        int s = wsum[lane];
#pragma unroll
        for (int o = 1; o < 4; o <<= 1) {
            int y = __shfl_up_sync(0x0000000Fu, s, o);
            if (lane >= o) s += y;
        }
        wsum[lane] = s;
    }
    __syncthreads();
    int incl = x + (w > 0 ? wsum[w - 1] : 0);
    if (t < nb) partials[t] = incl - v;
}

__global__ void scan3_kernel(int* __restrict__ off, const int* __restrict__ partials,
                             int* __restrict__ cur, const int* __restrict__ deg,
                             float* __restrict__ dinv, int n)
{
    int gid = blockIdx.x * blockDim.x + threadIdx.x;
    if (gid < n) {
        int o = off[gid] + partials[gid >> 10];
        off[gid] = o;
        cur[gid] = o;
        if (gid == n - 1) off[n] = o + deg[gid];
        dinv[gid] = rsqrtf((float)(deg[gid] + 1));   // +1 self loop
    }
}

__global__ void scatter_kernel(const int* __restrict__ src, const int* __restrict__ dst,
                               const float* __restrict__ dinv, int* __restrict__ cur,
                               int2* __restrict__ csr, int E)
{
    int e = blockIdx.x * blockDim.x + threadIdx.x;
    if (e >= E) return;
    int s = src[e], d = dst[e];
    int pos = atomicAdd(&cur[d], 1);
    csr[pos] = make_int2(s, __float_as_int(__ldg(&dinv[s])));
}

// ---------------------------------------------------------------------------
// GEMM (R8/R9-proven SIMT): xw = relu_fused(in) @ W. 128 rows/block as 4 x
// 32-row subtiles, W loaded once. Thread tile 4x4, dim3(DOUT/4, 8).
template<int DIN, int DOUT, bool FUSE>
__global__ void gemm_kernel(const float* __restrict__ in, const float* __restrict__ W,
                            const float* __restrict__ bprev, float* __restrict__ xw, int n)
{
    extern __shared__ float sh[];
    float* Ws = sh;                   // DIN*DOUT
    float* xs = sh + DIN * DOUT;      // 32*DIN
    const int tid  = threadIdx.y * blockDim.x + threadIdx.x;
    const int nthr = blockDim.x * blockDim.y;

    for (int i = tid; i < DIN * DOUT / 4; i += nthr)
        ((float4*)Ws)[i] = ((const float4*)W)[i];

    const int c0 = threadIdx.x * 4;
    const int r0 = threadIdx.y * 4;

#pragma unroll
    for (int t = 0; t < 4; t++) {
        const int row0 = blockIdx.x * 128 + t * 32;
        __syncthreads();   // xs reuse barrier (first pass: Ws ready too)
        for (int i = tid; i < 32 * DIN / 4; i += nthr) {
            int r = i / (DIN / 4), kk = i % (DIN / 4);
            int row = row0 + r;
            float4 v = make_float4(0.f, 0.f, 0.f, 0.f);
            if (row < n) {
                v = ((const float4*)(in + (size_t)row * DIN))[kk];
                if (FUSE) {
                    float4 b = ((const float4*)bprev)[kk];
                    v.x = fmaxf(v.x + b.x, 0.f);
                    v.y = fmaxf(v.y + b.y, 0.f);
                    v.z = fmaxf(v.z + b.z, 0.f);
                    v.w = fmaxf(v.w + b.w, 0.f);
                }
            }
            ((float4*)(xs + r * DIN))[kk] = v;
        }
        __syncthreads();

        float acc[4][4] = {};
#pragma unroll 4
        for (int k4 = 0; k4 < DIN; k4 += 4) {
            float4 a0 = *(const float4*)(xs + (r0 + 0) * DIN + k4);
            float4 a1 = *(const float4*)(xs + (r0 + 1) * DIN + k4);
            float4 a2 = *(const float4*)(xs + (r0 + 2) * DIN + k4);
            float4 a3 = *(const float4*)(xs + (r0 + 3) * DIN + k4);
#pragma unroll
            for (int j = 0; j < 4; j++) {
                float4 b = *(const float4*)(Ws + (k4 + j) * DOUT + c0);
                float e0 = j == 0 ? a0.x : j == 1 ? a0.y : j == 2 ? a0.z : a0.w;
                float e1 = j == 0 ? a1.x : j == 1 ? a1.y : j == 2 ? a1.z : a1.w;
                float e2 = j == 0 ? a2.x : j == 1 ? a2.y : j == 2 ? a2.z : a2.w;
                float e3 = j == 0 ? a3.x : j == 1 ? a3.y : j == 2 ? a3.z : a3.w;
                acc[0][0] = fmaf(e0, b.x, acc[0][0]);
                acc[0][1] = fmaf(e0, b.y, acc[0][1]);
                acc[0][2] = fmaf(e0, b.z, acc[0][2]);
                acc[0][3] = fmaf(e0, b.w, acc[0][3]);
                acc[1][0] = fmaf(e1, b.x, acc[1][0]);
                acc[1][1] = fmaf(e1, b.y, acc[1][1]);
                acc[1][2] = fmaf(e1, b.z, acc[1][2]);
                acc[1][3] = fmaf(e1, b.w, acc[1][3]);
                acc[2][0] = fmaf(e2, b.x, acc[2][0]);
                acc[2][1] = fmaf(e2, b.y, acc[2][1]);
                acc[2][2] = fmaf(e2, b.z, acc[2][2]);
                acc[2][3] = fmaf(e2, b.w, acc[2][3]);
                acc[3][0] = fmaf(e3, b.x, acc[3][0]);
                acc[3][1] = fmaf(e3, b.y, acc[3][1]);
                acc[3][2] = fmaf(e3, b.z, acc[3][2]);
                acc[3][3] = fmaf(e3, b.w, acc[3][3]);
            }
        }
#pragma unroll
        for (int i = 0; i < 4; i++) {
            int row = row0 + r0 + i;
            if (row >= n) continue;
            *(float4*)(xw + (size_t)row * DOUT + c0) =
                make_float4(acc[i][0], acc[i][1], acc[i][2], acc[i][3]);
        }
    }
}

// ---------------------------------------------------------------------------
// CSR aggregation: out[d] = feat[d]*dinv[d]^2 + sum_in dinv[s]*dinv[d]*feat[s].
template<int DOUT>
__global__ void agg_csr_kernel(const int* __restrict__ off, const int2* __restrict__ csr,
                               const float* __restrict__ xw, const float* __restrict__ dinv,
                               float* __restrict__ aggout, int n)
{
    constexpr int VEC = DOUT / 32;   // 4 or 2
    int node = blockIdx.x * 8 + (threadIdx.x >> 5);
    if (node >= n) return;
    int lane = threadIdx.x & 31;

    float dv = __ldg(&dinv[node]);
    const float* xr = xw + (size_t)node * DOUT + lane * VEC;
    float acc[VEC], acc2[VEC];
    if (VEC == 4) {
        float4 v = *(const float4*)xr;
        acc[0] = v.x * dv * dv; acc[1] = v.y * dv * dv;
        acc[2] = v.z * dv * dv; acc[3] = v.w * dv * dv;
        acc2[0] = acc2[1] = acc2[2] = acc2[3] = 0.f;
    } else {
        float2 v = *(const float2*)xr;
        acc[0] = v.x * dv * dv; acc[1] = v.y * dv * dv;
        acc2[0] = acc2[1] = 0.f;
    }

    int p = __ldg(&off[node]);
    int pend = __ldg(&off[node + 1]);
    for (; p + 2 <= pend; p += 2) {
        int2 e0 = __ldg(&csr[p]);
        int2 e1 = __ldg(&csr[p + 1]);
        float n0 = __int_as_float(e0.y) * dv;
        float n1 = __int_as_float(e1.y) * dv;
        const float* s0 = xw + (size_t)e0.x * DOUT + lane * VEC;
        const float* s1 = xw + (size_t)e1.x * DOUT + lane * VEC;
        if (VEC == 4) {
            float4 v0 = *(const float4*)s0;
            float4 v1 = *(const float4*)s1;
            acc[0] = fmaf(n0, v0.x, acc[0]); acc[1] = fmaf(n0, v0.y, acc[1]);
            acc[2] = fmaf(n0, v0.z, acc[2]); acc[3] = fmaf(n0, v0.w, acc[3]);
            acc2[0] = fmaf(n1, v1.x, acc2[0]); acc2[1] = fmaf(n1, v1.y, acc2[1]);
            acc2[2] = fmaf(n1, v1.z, acc2[2]); acc2[3] = fmaf(n1, v1.w, acc2[3]);
        } else {
            float2 v0 = *(const float2*)s0;
            float2 v1 = *(const float2*)s1;
            acc[0] = fmaf(n0, v0.x, acc[0]); acc[1] = fmaf(n0, v0.y, acc[1]);
            acc2[0] = fmaf(n1, v1.x, acc2[0]); acc2[1] = fmaf(n1, v1.y, acc2[1]);
        }
    }
    if (p < pend) {
        int2 e0 = __ldg(&csr[p]);
        float n0 = __int_as_float(e0.y) * dv;
        const float* s0 = xw + (size_t)e0.x * DOUT + lane * VEC;
        if (VEC == 4) {
            float4 v0 = *(const float4*)s0;
            acc[0] = fmaf(n0, v0.x, acc[0]); acc[1] = fmaf(n0, v0.y, acc[1]);
            acc[2] = fmaf(n0, v0.z, acc[2]); acc[3] = fmaf(n0, v0.w, acc[3]);
        } else {
            float2 v0 = *(const float2*)s0;
            acc[0] = fmaf(n0, v0.x, acc[0]); acc[1] = fmaf(n0, v0.y, acc[1]);
        }
    }

    float* o = aggout + (size_t)node * DOUT + lane * VEC;
    if (VEC == 4)
        *(float4*)o = make_float4(acc[0] + acc2[0], acc[1] + acc2[1],
                                  acc[2] + acc2[2], acc[3] + acc2[3]);
    else
        *(float2*)o = make_float2(acc[0] + acc2[0], acc[1] + acc2[1]);
}

// ---------------------------------------------------------------------------
__global__ void colsum_kernel(const float* __restrict__ agg, float* __restrict__ colsum, int n)
{
    __shared__ float sm[256];
    int c  = threadIdx.x & 63;
    int rl = threadIdx.x >> 6;
    float acc = 0.f;
    for (int row = blockIdx.x * 4 + rl; row < n; row += gridDim.x * 4)
        acc += agg[(size_t)row * 64 + c];
    sm[threadIdx.x] = acc;
    __syncthreads();
    if (threadIdx.x < 64) {
        float s = sm[c] + sm[64 + c] + sm[128 + c] + sm[192 + c];
        atomicAdd(&colsum[c], s);
    }
}

__global__ void gc_kernel(const float* __restrict__ colsum, const float* __restrict__ b2,
                          const float* __restrict__ Wa, float* __restrict__ gc, float invN)
{
    __shared__ float mean[64];
    int t = threadIdx.x;
    mean[t] = colsum[t] * invN + b2[t];
    __syncthreads();
    float acc = 0.f;
#pragma unroll
    for (int d = 0; d < 64; d++) acc += mean[d] * Wa[d * 64 + t];
    gc[t] = tanhf(acc);
}

__global__ void attpool_kernel(const float* __restrict__ agg, const float* __restrict__ b2,
                               const float* __restrict__ gc, float* __restrict__ h, int n)
{
    __shared__ float gcs[64], b2s[64];
    __shared__ float red[8][64];
    int tid = threadIdx.x;
    if (tid < 64) { gcs[tid] = gc[tid]; b2s[tid] = b2[tid]; }
    __syncthreads();
    int lane = tid & 31, w = tid >> 5;
    float gx = gcs[2 * lane], gy = gcs[2 * lane + 1];
    float bx = b2s[2 * lane], by = b2s[2 * lane + 1];
    float ax = 0.f, ay = 0.f;
    for (int row = blockIdx.x * 8 + w; row < n; row += gridDim.x * 8) {
        float2 v = *(const float2*)(agg + (size_t)row * 64 + 2 * lane);
        v.x += bx; v.y += by;
        float d = v.x * gx + v.y * gy;
#pragma unroll
        for (int o = 16; o; o >>= 1) d += __shfl_xor_sync(0xFFFFFFFFu, d, o);
        float att = 1.f / (1.f + expf(-d));
        ax += v.x * att; ay += v.y * att;
    }
    red[w][2 * lane] = ax; red[w][2 * lane + 1] = ay;
    __syncthreads();
    if (w == 0) {
        float sx = 0.f, sy = 0.f;
#pragma unroll
        for (int i = 0; i < 8; i++) { sx += red[i][2 * lane]; sy += red[i][2 * lane + 1]; }
        atomicAdd(&h[2 * lane], sx);
        atomicAdd(&h[2 * lane + 1], sy);
    }
}

// ---------------------------------------------------------------------------
__global__ void final_kernel(const float* __restrict__ h,
                             const float* __restrict__ Wt, const float* __restrict__ Wm,
                             const float* __restrict__ nb,
                             const float* __restrict__ w0, const float* __restrict__ bb0,
                             const float* __restrict__ w1, const float* __restrict__ bb1,
                             const float* __restrict__ w2, const float* __restrict__ bb2,
                             const float* __restrict__ w3, const float* __restrict__ bb3,
                             const float* __restrict__ sw, const float* __restrict__ sb,
                             float* __restrict__ out)
{
    __shared__ float hi[64], hj[64];
    __shared__ float part[1024];
    __shared__ float z[16];
    int t = threadIdx.x;
    if (t < 64) hi[t] = h[t];
    else if (t < 128) hj[t - 64] = h[t];
    __syncthreads();

    int k = t >> 6, e = t & 63;
    const float* wt = Wt + (size_t)k * 4096 + e;
    float acc = 0.f;
#pragma unroll
    for (int d = 0; d < 64; d++) acc += hi[d] * wt[d * 64];
    part[t] = acc * hj[e];
    __syncthreads();

    if (t < 16) {
        float s = 0.f;
        for (int e2 = 0; e2 < 64; e2++) s += part[t * 64 + e2];
        float lin = 0.f;
        const float* wm = Wm + t * 128;
        for (int m = 0; m < 64; m++) lin += wm[m] * hi[m] + wm[64 + m] * hj[m];
        z[t] = tanhf(s + lin + nb[t]);
    }
    __syncthreads();

    if (t == 0) {
        float a[32], b[32];
        for (int j = 0; j < 32; j++) { float s = bb0[j]; for (int i = 0; i < 16; i++) s += z[i] * w0[i * 32 + j]; a[j] = fmaxf(s, 0.f); }
        for (int j = 0; j < 16; j++) { float s = bb1[j]; for (int i = 0; i < 32; i++) s += a[i] * w1[i * 16 + j]; b[j] = fmaxf(s, 0.f); }
        for (int j = 0; j <  8; j++) { float s = bb2[j]; for (int i = 0; i < 16; i++) s += b[i] * w2[i * 8 + j];  a[j] = fmaxf(s, 0.f); }
        for (int j = 0; j <  4; j++) { float s = bb3[j]; for (int i = 0; i <  8; i++) s += a[i] * w3[i * 4 + j];  b[j] = fmaxf(s, 0.f); }
        float s = sb[0];
        for (int i = 0; i < 4; i++) s += b[i] * sw[i];
        out[0] = s;
    }
}

// ---------------------------------------------------------------------------
extern "C" void kernel_launch(void* const* d_in, const int* in_sizes, int n_in,
                              void* d_out, int out_size)
{
    const float* x_i = (const float*)d_in[0];
    const int*   ei  = (const int*)d_in[1];     // int32 (JAX x64 disabled)
    const float* x_j = (const float*)d_in[2];
    const int*   ej  = (const int*)d_in[3];
    const float* w0 = (const float*)d_in[4];
    const float* b0 = (const float*)d_in[5];
    const float* w1 = (const float*)d_in[6];
    const float* b1 = (const float*)d_in[7];
    const float* w2 = (const float*)d_in[8];
    const float* b2 = (const float*)d_in[9];
    const float* att_w  = (const float*)d_in[10];
    const float* ntn_wt = (const float*)d_in[11];
    const float* ntn_wm = (const float*)d_in[12];
    const float* ntn_b  = (const float*)d_in[13];
    const float* mw0 = (const float*)d_in[14];
    const float* mb0 = (const float*)d_in[15];
    const float* mw1 = (const float*)d_in[16];
    const float* mb1 = (const float*)d_in[17];
    const float* mw2 = (const float*)d_in[18];
    const float* mb2 = (const float*)d_in[19];
    const float* mw3 = (const float*)d_in[20];
    const float* mb3 = (const float*)d_in[21];
    const float* sw  = (const float*)d_in[22];
    const float* sb  = (const float*)d_in[23];
    float* out = (float*)d_out;

    const int N = in_sizes[0] / 64;
    const int E = in_sizes[1] / 2;

    float *bufA, *bufB, *bufC, *dinvp, *colsump, *gcp, *hp;
    int *degp, *offp, *curp, *partp;
    int2* csrp;
    cudaGetSymbolAddress((void**)&bufA,    g_bufA);
    cudaGetSymbolAddress((void**)&bufB,    g_bufB);
    cudaGetSymbolAddress((void**)&bufC,    g_bufC);
    cudaGetSymbolAddress((void**)&dinvp,   g_dinv);
    cudaGetSymbolAddress((void**)&degp,    g_deg);
    cudaGetSymbolAddress((void**)&offp,    g_off);
    cudaGetSymbolAddress((void**)&curp,    g_cur);
    cudaGetSymbolAddress((void**)&partp,   g_part);
    cudaGetSymbolAddress((void**)&csrp,    g_csr);
    cudaGetSymbolAddress((void**)&colsump, g_colsum);
    cudaGetSymbolAddress((void**)&gcp,     g_gc);
    cudaGetSymbolAddress((void**)&hp,      g_h);

    const int smem0 = (64  * 128 + 32 * 64 ) * 4;   // 40960
    const int smem1 = (128 * 128 + 32 * 128) * 4;   // 81920
    const int smem2 = (128 * 64  + 32 * 128) * 4;   // 49152
    cudaFuncSetAttribute(gemm_kernel<64, 128, false>, cudaFuncAttributeMaxDynamicSharedMemorySize, smem0);
    cudaFuncSetAttribute(gemm_kernel<128, 128, true>, cudaFuncAttributeMaxDynamicSharedMemorySize, smem1);
    cudaFuncSetAttribute(gemm_kernel<128, 64,  true>, cudaFuncAttributeMaxDynamicSharedMemorySize, smem2);

    const int gemm_blocks = (N + 127) / 128;
    const int agg_blocks  = (N + 7) / 8;
    const int scan_blocks = (N + 1023) / 1024;
    const int nb256 = (N + 255) / 256;
    const int eb256 = (E + 255) / 256;

    cudaStream_t s0 = 0;          // captured legacy stream (graph 0)
    cudaStream_t s1 = g_s2;       // forked stream (graph 1)

    zero_all_kernel<<<(2 * N + 255) / 256, 256, 0, s0>>>(degp, hp, colsump, 2 * N);
    cudaEventRecord(g_evFork, s0);
    cudaStreamWaitEvent(s1, g_evFork, 0);

    // ================= graph 0 (s0): GEMM-first phase =================
    {
        const int g = 0;
        const int* src = ei;
        const int* dst = ei + E;
        int*   dg   = degp;
        int*   off  = offp;
        int*   cur  = curp;
        int*   part = partp;
        float* dnv  = dinvp;
        int2*  csr  = csrp;
        float* bA = bufA; float* bB = bufB; float* bC = bufC;
        (void)g;

        // FMA-heavy first (no CSR dependency)
        gemm_kernel<64, 128, false><<<gemm_blocks, dim3(32, 8), smem0, s0>>>(x_i, w0, nullptr, bB, N);
        // CSR build
        deg_kernel<<<eb256, 256, 0, s0>>>(dst, dg, E);
        scan1_kernel<<<scan_blocks, 1024, 0, s0>>>(dg, off, part, N);
        scan2_kernel<<<1, 128, 0, s0>>>(part, scan_blocks);
        scan3_kernel<<<nb256, 256, 0, s0>>>(off, part, cur, dg, dnv, N);
        scatter_kernel<<<eb256, 256, 0, s0>>>(src, dst, dnv, cur, csr, E);
        // L0 aggregate, L1, L2
        agg_csr_kernel<128><<<agg_blocks, 256, 0, s0>>>(off, csr, bB, dnv, bA, N);
        gemm_kernel<128, 128, true><<<gemm_blocks, dim3(32, 8), smem1, s0>>>(bA, w1, b0, bC, N);
        agg_csr_kernel<128><<<agg_blocks, 256, 0, s0>>>(off, csr, bC, dnv, bA, N);
        gemm_kernel<128, 64, true><<<gemm_blocks, dim3(16, 8), smem2, s0>>>(bA, w2, b1, bB, N);
        agg_csr_kernel<64><<<agg_blocks, 256, 0, s0>>>(off, csr, bB, dnv, bC, N);
        // Pooling
        colsum_kernel<<<512, 256, 0, s0>>>(bC, colsump, N);
        gc_kernel<<<1, 64, 0, s0>>>(colsump, b2, att_w, gcp, 1.0f / (float)N);
        attpool_kernel<<<592, 256, 0, s0>>>(bC, b2, gcp, hp, N);
    }

    // ================= graph 1 (s1): CSR + aggregate-first phase ======
    {
        const int* src = ej;
        const int* dst = ej + E;
        int*   dg   = degp + MAXN;
        int*   off  = offp + (MAXN + 1);
        int*   cur  = curp + MAXN;
        int*   part = partp + 256;
        float* dnv  = dinvp + MAXN;
        int2*  csr  = csrp + (size_t)MAXE;
        float* bA = bufA + XCAP; float* bB = bufB + XCAP; float* bC = bufC + XCAP;

        // L2-heavy first: CSR build while s0 runs its L0 GEMM
        deg_kernel<<<eb256, 256, 0, s1>>>(dst, dg, E);
        scan1_kernel<<<scan_blocks, 1024, 0, s1>>>(dg, off, part, N);
        scan2_kernel<<<1, 128, 0, s1>>>(part, scan_blocks);
        scan3_kernel<<<nb256, 256, 0, s1>>>(off, part, cur, dg, dnv, N);
        scatter_kernel<<<eb256, 256, 0, s1>>>(src, dst, dnv, cur, csr, E);
        // L0 aggregate-first (64 cols: half the gather traffic), then GEMM
        agg_csr_kernel<64><<<agg_blocks, 256, 0, s1>>>(off, csr, x_j, dnv, bC, N);
        gemm_kernel<64, 128, false><<<gemm_blocks, dim3(32, 8), smem0, s1>>>(bC, w0, nullptr, bA, N);
        // L1
        gemm_kernel<128, 128, true><<<gemm_blocks, dim3(32, 8), smem1, s1>>>(bA, w1, b0, bC, N);
        agg_csr_kernel<128><<<agg_blocks, 256, 0, s1>>>(off, csr, bC, dnv, bA, N);
        // L2
        gemm_kernel<128, 64, true><<<gemm_blocks, dim3(16, 8), smem2, s1>>>(bA, w2, b1, bB, N);
        agg_csr_kernel<64><<<agg_blocks, 256, 0, s1>>>(off, csr, bB, dnv, bC, N);
        // Pooling
        colsum_kernel<<<512, 256, 0, s1>>>(bC, colsump + 64, N);
        gc_kernel<<<1, 64, 0, s1>>>(colsump + 64, b2, att_w, gcp + 64, 1.0f / (float)N);
        attpool_kernel<<<592, 256, 0, s1>>>(bC, b2, gcp + 64, hp + 64, N);
    }

    cudaEventRecord(g_evJoin, s1);
    cudaStreamWaitEvent(s0, g_evJoin, 0);

    final_kernel<<<1, 1024, 0, s0>>>(hp, ntn_wt, ntn_wm, ntn_b,
                                     mw0, mb0, mw1, mb1, mw2, mb2, mw3, mb3,
                                     sw, sb, out);
}

// round 12
// speedup vs baseline: 1.2066x; 1.0855x over previous
#include <cuda_runtime.h>
#include <cuda_fp16.h>
#include <math.h>

// ---------------------------------------------------------------------------
// SimGNN on GB300: two anti-phased streams; GEMM outputs stored fp16 to halve
// the L2 gather traffic of CSR aggregation (all math fp32).
// ---------------------------------------------------------------------------

#define MAXN 100000
#define MAXE 1300000
#define XCAP ((size_t)MAXN * 128)

__device__ __align__(16) float g_bufA[2 * XCAP];   // fp32 agg outputs / gemm inputs
__device__ __align__(16) float g_bufB[2 * XCAP];   // carved into fp16 xw buffers
__device__ __align__(16) float g_bufC[2 * XCAP];   // fp32 final agg / pooling input
__device__ __align__(16) float g_dinv[2 * MAXN];
__device__ __align__(16) int   g_deg [2 * MAXN];
__device__ __align__(16) int   g_off [2 * (MAXN + 1)];
__device__ __align__(16) int   g_cur [2 * MAXN];
__device__ __align__(16) int   g_part[2 * 256];
__device__ __align__(16) int2  g_csr [2 * (size_t)MAXE];
__device__ __align__(16) float g_colsum[2 * 64];
__device__ __align__(16) float g_gc[2 * 64];
__device__ __align__(16) float g_h[128];

static cudaStream_t g_s2;
static cudaEvent_t  g_evFork, g_evJoin;
namespace {
struct StreamInit {
    StreamInit() {
        cudaStreamCreateWithFlags(&g_s2, cudaStreamNonBlocking);
        cudaEventCreateWithFlags(&g_evFork, cudaEventDisableTiming);
        cudaEventCreateWithFlags(&g_evJoin, cudaEventDisableTiming);
    }
};
static StreamInit s_streamInit;
}

// ------------------------- type-generic loads/stores -----------------------
__device__ __forceinline__ float4 load4(const float* p) { return *(const float4*)p; }
__device__ __forceinline__ float4 load4(const __half* p) {
    const __half2* h = (const __half2*)p;
    float2 a = __half22float2(h[0]);
    float2 b = __half22float2(h[1]);
    return make_float4(a.x, a.y, b.x, b.y);
}
__device__ __forceinline__ float2 load2(const float* p) { return *(const float2*)p; }
__device__ __forceinline__ float2 load2(const __half* p) {
    return __half22float2(*(const __half2*)p);
}
__device__ __forceinline__ void store4h(__half* p, float4 v) {
    __half2* h = (__half2*)p;
    h[0] = __floats2half2_rn(v.x, v.y);
    h[1] = __floats2half2_rn(v.z, v.w);
}

// ---------------------------------------------------------------------------
__global__ void zero_all_kernel(int* __restrict__ deg, float* __restrict__ h,
                                float* __restrict__ colsum, int n2)
{
    int i = blockIdx.x * blockDim.x + threadIdx.x;
    if (i < n2) deg[i] = 0;
    if (i < 128) { h[i] = 0.f; colsum[i] = 0.f; }
}

__global__ void deg_kernel(const int* __restrict__ dst, int* __restrict__ deg, int E) {
    int i = blockIdx.x * blockDim.x + threadIdx.x;
    if (i < E) atomicAdd(&deg[dst[i]], 1);
}

// --------------------------- CSR build: scan ------------------------------
__global__ void scan1_kernel(const int* __restrict__ deg, int* __restrict__ off,
                             int* __restrict__ partials, int n)
{
    __shared__ int wsum[32];
    int gid  = blockIdx.x * 1024 + threadIdx.x;
    int lane = threadIdx.x & 31, wid = threadIdx.x >> 5;
    int v = (gid < n) ? deg[gid] : 0;
    int x = v;
#pragma unroll
    for (int o = 1; o < 32; o <<= 1) {
        int y = __shfl_up_sync(0xFFFFFFFFu, x, o);
        if (lane >= o) x += y;
    }
    if (lane == 31) wsum[wid] = x;
    __syncthreads();
    if (wid == 0) {
        int s = wsum[lane];
#pragma unroll
        for (int o = 1; o < 32; o <<= 1) {
            int y = __shfl_up_sync(0xFFFFFFFFu, s, o);
            if (lane >= o) s += y;
        }
        wsum[lane] = s;
    }
    __syncthreads();
    int excl = (wid > 0 ? wsum[wid - 1] : 0) + x - v;
    if (gid < n) off[gid] = excl;
    if (threadIdx.x == 1023) partials[blockIdx.x] = wsum[31];
}

__global__ void scan2_kernel(int* __restrict__ partials, int nb)
{
    __shared__ int wsum[4];
    int t = threadIdx.x;
    int lane = t & 31, w = t >> 5;
    int v = (t < nb) ? partials[t] : 0;
    int x = v;
#pragma unroll
    for (int o = 1; o < 32; o <<= 1) {
        int y = __shfl_up_sync(0xFFFFFFFFu, x, o);
        if (lane >= o) x += y;
    }
    if (lane == 31) wsum[w] = x;
    __syncthreads();
    if (w == 0 && lane < 4) {
        int s = wsum[lane];
#pragma unroll
        for (int o = 1; o < 4; o <<= 1) {
            int y = __shfl_up_sync(0x0000000Fu, s, o);
            if (lane >= o) s += y;
        }
        wsum[lane] = s;
    }
    __syncthreads();
    int incl = x + (w > 0 ? wsum[w - 1] : 0);
    if (t < nb) partials[t] = incl - v;
}

__global__ void scan3_kernel(int* __restrict__ off, const int* __restrict__ partials,
                             int* __restrict__ cur, const int* __restrict__ deg,
                             float* __restrict__ dinv, int n)
{
    int gid = blockIdx.x * blockDim.x + threadIdx.x;
    if (gid < n) {
        int o = off[gid] + partials[gid >> 10];
        off[gid] = o;
        cur[gid] = o;
        if (gid == n - 1) off[n] = o + deg[gid];
        dinv[gid] = rsqrtf((float)(deg[gid] + 1));
    }
}

__global__ void scatter_kernel(const int* __restrict__ src, const int* __restrict__ dst,
                               const float* __restrict__ dinv, int* __restrict__ cur,
                               int2* __restrict__ csr, int E)
{
    int e = blockIdx.x * blockDim.x + threadIdx.x;
    if (e >= E) return;
    int s = src[e], d = dst[e];
    int pos = atomicAdd(&cur[d], 1);
    csr[pos] = make_int2(s, __float_as_int(__ldg(&dinv[s])));
}

// ---------------------------------------------------------------------------
// GEMM: xwH (fp16) = relu_fused(in) @ W. 128 rows/block as 4 x 32-row
// subtiles, W loaded once. Thread tile 4x4, dim3(DOUT/4, 8). Input fp32 or
// fp16 (TIN); staged/accumulated fp32; output stored fp16.
template<typename TIN, int DIN, int DOUT, bool FUSE>
__global__ void gemm_kernel(const TIN* __restrict__ in, const float* __restrict__ W,
                            const float* __restrict__ bprev, __half* __restrict__ xw, int n)
{
    extern __shared__ float sh[];
    float* Ws = sh;                   // DIN*DOUT
    float* xs = sh + DIN * DOUT;      // 32*DIN
    const int tid  = threadIdx.y * blockDim.x + threadIdx.x;
    const int nthr = blockDim.x * blockDim.y;

    for (int i = tid; i < DIN * DOUT / 4; i += nthr)
        ((float4*)Ws)[i] = ((const float4*)W)[i];

    const int c0 = threadIdx.x * 4;
    const int r0 = threadIdx.y * 4;

#pragma unroll
    for (int t = 0; t < 4; t++) {
        const int row0 = blockIdx.x * 128 + t * 32;
        __syncthreads();
        for (int i = tid; i < 32 * DIN / 4; i += nthr) {
            int r = i / (DIN / 4), kk = i % (DIN / 4);
            int row = row0 + r;
            float4 v = make_float4(0.f, 0.f, 0.f, 0.f);
            if (row < n) {
                v = load4(in + (size_t)row * DIN + kk * 4);
                if (FUSE) {
                    float4 b = ((const float4*)bprev)[kk];
                    v.x = fmaxf(v.x + b.x, 0.f);
                    v.y = fmaxf(v.y + b.y, 0.f);
                    v.z = fmaxf(v.z + b.z, 0.f);
                    v.w = fmaxf(v.w + b.w, 0.f);
                }
            }
            ((float4*)(xs + r * DIN))[kk] = v;
        }
        __syncthreads();

        float acc[4][4] = {};
#pragma unroll 4
        for (int k4 = 0; k4 < DIN; k4 += 4) {
            float4 a0 = *(const float4*)(xs + (r0 + 0) * DIN + k4);
            float4 a1 = *(const float4*)(xs + (r0 + 1) * DIN + k4);
            float4 a2 = *(const float4*)(xs + (r0 + 2) * DIN + k4);
            float4 a3 = *(const float4*)(xs + (r0 + 3) * DIN + k4);
#pragma unroll
            for (int j = 0; j < 4; j++) {
                float4 b = *(const float4*)(Ws + (k4 + j) * DOUT + c0);
                float e0 = j == 0 ? a0.x : j == 1 ? a0.y : j == 2 ? a0.z : a0.w;
                float e1 = j == 0 ? a1.x : j == 1 ? a1.y : j == 2 ? a1.z : a1.w;
                float e2 = j == 0 ? a2.x : j == 1 ? a2.y : j == 2 ? a2.z : a2.w;
                float e3 = j == 0 ? a3.x : j == 1 ? a3.y : j == 2 ? a3.z : a3.w;
                acc[0][0] = fmaf(e0, b.x, acc[0][0]);
                acc[0][1] = fmaf(e0, b.y, acc[0][1]);
                acc[0][2] = fmaf(e0, b.z, acc[0][2]);
                acc[0][3] = fmaf(e0, b.w, acc[0][3]);
                acc[1][0] = fmaf(e1, b.x, acc[1][0]);
                acc[1][1] = fmaf(e1, b.y, acc[1][1]);
                acc[1][2] = fmaf(e1, b.z, acc[1][2]);
                acc[1][3] = fmaf(e1, b.w, acc[1][3]);
                acc[2][0] = fmaf(e2, b.x, acc[2][0]);
                acc[2][1] = fmaf(e2, b.y, acc[2][1]);
                acc[2][2] = fmaf(e2, b.z, acc[2][2]);
                acc[2][3] = fmaf(e2, b.w, acc[2][3]);
                acc[3][0] = fmaf(e3, b.x, acc[3][0]);
                acc[3][1] = fmaf(e3, b.y, acc[3][1]);
                acc[3][2] = fmaf(e3, b.z, acc[3][2]);
                acc[3][3] = fmaf(e3, b.w, acc[3][3]);
            }
        }
#pragma unroll
        for (int i = 0; i < 4; i++) {
            int row = row0 + r0 + i;
            if (row >= n) continue;
            store4h(xw + (size_t)row * DOUT + c0,
                    make_float4(acc[i][0], acc[i][1], acc[i][2], acc[i][3]));
        }
    }
}

// ---------------------------------------------------------------------------
// CSR aggregation (fp32 accumulate, TIN gather):
// out[d] = feat[d]*dinv[d]^2 + sum_in dinv[s]*dinv[d]*feat[s].
template<typename TIN, int DOUT>
__global__ void agg_csr_kernel(const int* __restrict__ off, const int2* __restrict__ csr,
                               const TIN* __restrict__ xw, const float* __restrict__ dinv,
                               float* __restrict__ aggout, int n)
{
    constexpr int VEC = DOUT / 32;   // 4 or 2
    int node = blockIdx.x * 8 + (threadIdx.x >> 5);
    if (node >= n) return;
    int lane = threadIdx.x & 31;

    float dv = __ldg(&dinv[node]);
    const TIN* xr = xw + (size_t)node * DOUT + lane * VEC;
    float acc[VEC], acc2[VEC];
    if (VEC == 4) {
        float4 v = load4(xr);
        acc[0] = v.x * dv * dv; acc[1] = v.y * dv * dv;
        acc[2] = v.z * dv * dv; acc[3] = v.w * dv * dv;
        acc2[0] = acc2[1] = acc2[2] = acc2[3] = 0.f;
    } else {
        float2 v = load2(xr);
        acc[0] = v.x * dv * dv; acc[1] = v.y * dv * dv;
        acc2[0] = acc2[1] = 0.f;
    }

    int p = __ldg(&off[node]);
    int pend = __ldg(&off[node + 1]);
    for (; p + 2 <= pend; p += 2) {
        int2 e0 = __ldg(&csr[p]);
        int2 e1 = __ldg(&csr[p + 1]);
        float n0 = __int_as_float(e0.y) * dv;
        float n1 = __int_as_float(e1.y) * dv;
        const TIN* s0 = xw + (size_t)e0.x * DOUT + lane * VEC;
        const TIN* s1 = xw + (size_t)e1.x * DOUT + lane * VEC;
        if (VEC == 4) {
            float4 v0 = load4(s0);
            float4 v1 = load4(s1);
            acc[0] = fmaf(n0, v0.x, acc[0]); acc[1] = fmaf(n0, v0.y, acc[1]);
            acc[2] = fmaf(n0, v0.z, acc[2]); acc[3] = fmaf(n0, v0.w, acc[3]);
            acc2[0] = fmaf(n1, v1.x, acc2[0]); acc2[1] = fmaf(n1, v1.y, acc2[1]);
            acc2[2] = fmaf(n1, v1.z, acc2[2]); acc2[3] = fmaf(n1, v1.w, acc2[3]);
        } else {
            float2 v0 = load2(s0);
            float2 v1 = load2(s1);
            acc[0] = fmaf(n0, v0.x, acc[0]); acc[1] = fmaf(n0, v0.y, acc[1]);
            acc2[0] = fmaf(n1, v1.x, acc2[0]); acc2[1] = fmaf(n1, v1.y, acc2[1]);
        }
    }
    if (p < pend) {
        int2 e0 = __ldg(&csr[p]);
        float n0 = __int_as_float(e0.y) * dv;
        const TIN* s0 = xw + (size_t)e0.x * DOUT + lane * VEC;
        if (VEC == 4) {
            float4 v0 = load4(s0);
            acc[0] = fmaf(n0, v0.x, acc[0]); acc[1] = fmaf(n0, v0.y, acc[1]);
            acc[2] = fmaf(n0, v0.z, acc[2]); acc[3] = fmaf(n0, v0.w, acc[3]);
        } else {
            float2 v0 = load2(s0);
            acc[0] = fmaf(n0, v0.x, acc[0]); acc[1] = fmaf(n0, v0.y, acc[1]);
        }
    }

    float* o = aggout + (size_t)node * DOUT + lane * VEC;
    if (VEC == 4)
        *(float4*)o = make_float4(acc[0] + acc2[0], acc[1] + acc2[1],
                                  acc[2] + acc2[2], acc[3] + acc2[3]);
    else
        *(float2*)o = make_float2(acc[0] + acc2[0], acc[1] + acc2[1]);
}

// ---------------------------------------------------------------------------
__global__ void colsum_kernel(const float* __restrict__ agg, float* __restrict__ colsum, int n)
{
    __shared__ float sm[256];
    int c  = threadIdx.x & 63;
    int rl = threadIdx.x >> 6;
    float acc = 0.f;
    for (int row = blockIdx.x * 4 + rl; row < n; row += gridDim.x * 4)
        acc += agg[(size_t)row * 64 + c];
    sm[threadIdx.x] = acc;
    __syncthreads();
    if (threadIdx.x < 64) {
        float s = sm[c] + sm[64 + c] + sm[128 + c] + sm[192 + c];
        atomicAdd(&colsum[c], s);
    }
}

__global__ void gc_kernel(const float* __restrict__ colsum, const float* __restrict__ b2,
                          const float* __restrict__ Wa, float* __restrict__ gc, float invN)
{
    __shared__ float mean[64];
    int t = threadIdx.x;
    mean[t] = colsum[t] * invN + b2[t];
    __syncthreads();
    float acc = 0.f;
#pragma unroll
    for (int d = 0; d < 64; d++) acc += mean[d] * Wa[d * 64 + t];
    gc[t] = tanhf(acc);
}

__global__ void attpool_kernel(const float* __restrict__ agg, const float* __restrict__ b2,
                               const float* __restrict__ gc, float* __restrict__ h, int n)
{
    __shared__ float gcs[64], b2s[64];
    __shared__ float red[8][64];
    int tid = threadIdx.x;
    if (tid < 64) { gcs[tid] = gc[tid]; b2s[tid] = b2[tid]; }
    __syncthreads();
    int lane = tid & 31, w = tid >> 5;
    float gx = gcs[2 * lane], gy = gcs[2 * lane + 1];
    float bx = b2s[2 * lane], by = b2s[2 * lane + 1];
    float ax = 0.f, ay = 0.f;
    for (int row = blockIdx.x * 8 + w; row < n; row += gridDim.x * 8) {
        float2 v = *(const float2*)(agg + (size_t)row * 64 + 2 * lane);
        v.x += bx; v.y += by;
        float d = v.x * gx + v.y * gy;
#pragma unroll
        for (int o = 16; o; o >>= 1) d += __shfl_xor_sync(0xFFFFFFFFu, d, o);
        float att = 1.f / (1.f + expf(-d));
        ax += v.x * att; ay += v.y * att;
    }
    red[w][2 * lane] = ax; red[w][2 * lane + 1] = ay;
    __syncthreads();
    if (w == 0) {
        float sx = 0.f, sy = 0.f;
#pragma unroll
        for (int i = 0; i < 8; i++) { sx += red[i][2 * lane]; sy += red[i][2 * lane + 1]; }
        atomicAdd(&h[2 * lane], sx);
        atomicAdd(&h[2 * lane + 1], sy);
    }
}

// ---------------------------------------------------------------------------
__global__ void final_kernel(const float* __restrict__ h,
                             const float* __restrict__ Wt, const float* __restrict__ Wm,
                             const float* __restrict__ nb,
                             const float* __restrict__ w0, const float* __restrict__ bb0,
                             const float* __restrict__ w1, const float* __restrict__ bb1,
                             const float* __restrict__ w2, const float* __restrict__ bb2,
                             const float* __restrict__ w3, const float* __restrict__ bb3,
                             const float* __restrict__ sw, const float* __restrict__ sb,
                             float* __restrict__ out)
{
    __shared__ float hi[64], hj[64];
    __shared__ float part[1024];
    __shared__ float z[16];
    int t = threadIdx.x;
    if (t < 64) hi[t] = h[t];
    else if (t < 128) hj[t - 64] = h[t];
    __syncthreads();

    int k = t >> 6, e = t & 63;
    const float* wt = Wt + (size_t)k * 4096 + e;
    float acc = 0.f;
#pragma unroll
    for (int d = 0; d < 64; d++) acc += hi[d] * wt[d * 64];
    part[t] = acc * hj[e];
    __syncthreads();

    if (t < 16) {
        float s = 0.f;
        for (int e2 = 0; e2 < 64; e2++) s += part[t * 64 + e2];
        float lin = 0.f;
        const float* wm = Wm + t * 128;
        for (int m = 0; m < 64; m++) lin += wm[m] * hi[m] + wm[64 + m] * hj[m];
        z[t] = tanhf(s + lin + nb[t]);
    }
    __syncthreads();

    if (t == 0) {
        float a[32], b[32];
        for (int j = 0; j < 32; j++) { float s = bb0[j]; for (int i = 0; i < 16; i++) s += z[i] * w0[i * 32 + j]; a[j] = fmaxf(s, 0.f); }
        for (int j = 0; j < 16; j++) { float s = bb1[j]; for (int i = 0; i < 32; i++) s += a[i] * w1[i * 16 + j]; b[j] = fmaxf(s, 0.f); }
        for (int j = 0; j <  8; j++) { float s = bb2[j]; for (int i = 0; i < 16; i++) s += b[i] * w2[i * 8 + j];  a[j] = fmaxf(s, 0.f); }
        for (int j = 0; j <  4; j++) { float s = bb3[j]; for (int i = 0; i <  8; i++) s += a[i] * w3[i * 4 + j];  b[j] = fmaxf(s, 0.f); }
        float s = sb[0];
        for (int i = 0; i < 4; i++) s += b[i] * sw[i];
        out[0] = s;
    }
}

// ---------------------------------------------------------------------------
extern "C" void kernel_launch(void* const* d_in, const int* in_sizes, int n_in,
                              void* d_out, int out_size)
{
    const float* x_i = (const float*)d_in[0];
    const int*   ei  = (const int*)d_in[1];     // int32 (JAX x64 disabled)
    const float* x_j = (const float*)d_in[2];
    const int*   ej  = (const int*)d_in[3];
    const float* w0 = (const float*)d_in[4];
    const float* b0 = (const float*)d_in[5];
    const float* w1 = (const float*)d_in[6];
    const float* b1 = (const float*)d_in[7];
    const float* w2 = (const float*)d_in[8];
    const float* b2 = (const float*)d_in[9];
    const float* att_w  = (const float*)d_in[10];
    const float* ntn_wt = (const float*)d_in[11];
    const float* ntn_wm = (const float*)d_in[12];
    const float* ntn_b  = (const float*)d_in[13];
    const float* mw0 = (const float*)d_in[14];
    const float* mb0 = (const float*)d_in[15];
    const float* mw1 = (const float*)d_in[16];
    const float* mb1 = (const float*)d_in[17];
    const float* mw2 = (const float*)d_in[18];
    const float* mb2 = (const float*)d_in[19];
    const float* mw3 = (const float*)d_in[20];
    const float* mb3 = (const float*)d_in[21];
    const float* sw  = (const float*)d_in[22];
    const float* sb  = (const float*)d_in[23];
    float* out = (float*)d_out;

    const int N = in_sizes[0] / 64;
    const int E = in_sizes[1] / 2;

    float *bufA, *bufB, *bufC, *dinvp, *colsump, *gcp, *hp;
    int *degp, *offp, *curp, *partp;
    int2* csrp;
    cudaGetSymbolAddress((void**)&bufA,    g_bufA);
    cudaGetSymbolAddress((void**)&bufB,    g_bufB);
    cudaGetSymbolAddress((void**)&bufC,    g_bufC);
    cudaGetSymbolAddress((void**)&dinvp,   g_dinv);
    cudaGetSymbolAddress((void**)&degp,    g_deg);
    cudaGetSymbolAddress((void**)&offp,    g_off);
    cudaGetSymbolAddress((void**)&curp,    g_cur);
    cudaGetSymbolAddress((void**)&partp,   g_part);
    cudaGetSymbolAddress((void**)&csrp,    g_csr);
    cudaGetSymbolAddress((void**)&colsump, g_colsum);
    cudaGetSymbolAddress((void**)&gcp,     g_gc);
    cudaGetSymbolAddress((void**)&hp,      g_h);

    const int smem0 = (64  * 128 + 32 * 64 ) * 4;   // 40960
    const int smem1 = (128 * 128 + 32 * 128) * 4;   // 81920
    const int smem2 = (128 * 64  + 32 * 128) * 4;   // 49152
    cudaFuncSetAttribute(gemm_kernel<float, 64, 128, false>, cudaFuncAttributeMaxDynamicSharedMemorySize, smem0);
    cudaFuncSetAttribute(gemm_kernel<float, 128, 128, true>, cudaFuncAttributeMaxDynamicSharedMemorySize, smem1);
    cudaFuncSetAttribute(gemm_kernel<__half, 128, 128, true>, cudaFuncAttributeMaxDynamicSharedMemorySize, smem1);
    cudaFuncSetAttribute(gemm_kernel<float, 128, 64,  true>, cudaFuncAttributeMaxDynamicSharedMemorySize, smem2);

    const int gemm_blocks = (N + 127) / 128;
    const int agg_blocks  = (N + 7) / 8;
    const int scan_blocks = (N + 1023) / 1024;
    const int nb256 = (N + 255) / 256;
    const int eb256 = (E + 255) / 256;

    cudaStream_t s0 = 0;          // captured legacy stream (graph 0)
    cudaStream_t s1 = g_s2;       // forked stream (graph 1)

    zero_all_kernel<<<(2 * N + 255) / 256, 256, 0, s0>>>(degp, hp, colsump, 2 * N);
    cudaEventRecord(g_evFork, s0);
    cudaStreamWaitEvent(s1, g_evFork, 0);

    // ================= graph 0 (s0): GEMM-first phase =================
    {
        const int* src = ei;
        const int* dst = ei + E;
        int*   dg   = degp;
        int*   off  = offp;
        int*   cur  = curp;
        int*   part = partp;
        float* dnv  = dinvp;
        int2*  csr  = csrp;
        float* bA = bufA;
        float* bC = bufC;
        __half* hA = (__half*)bufB;          // XCAP halves

        // FMA-heavy first (no CSR dependency)
        gemm_kernel<float, 64, 128, false><<<gemm_blocks, dim3(32, 8), smem0, s0>>>(x_i, w0, nullptr, hA, N);
        // CSR build
        deg_kernel<<<eb256, 256, 0, s0>>>(dst, dg, E);
        scan1_kernel<<<scan_blocks, 1024, 0, s0>>>(dg, off, part, N);
        scan2_kernel<<<1, 128, 0, s0>>>(part, scan_blocks);
        scan3_kernel<<<nb256, 256, 0, s0>>>(off, part, cur, dg, dnv, N);
        scatter_kernel<<<eb256, 256, 0, s0>>>(src, dst, dnv, cur, csr, E);
        // L0 aggregate, L1, L2
        agg_csr_kernel<__half, 128><<<agg_blocks, 256, 0, s0>>>(off, csr, hA, dnv, bA, N);
        gemm_kernel<float, 128, 128, true><<<gemm_blocks, dim3(32, 8), smem1, s0>>>(bA, w1, b0, hA, N);
        agg_csr_kernel<__half, 128><<<agg_blocks, 256, 0, s0>>>(off, csr, hA, dnv, bA, N);
        gemm_kernel<float, 128, 64, true><<<gemm_blocks, dim3(16, 8), smem2, s0>>>(bA, w2, b1, hA, N);
        agg_csr_kernel<__half, 64><<<agg_blocks, 256, 0, s0>>>(off, csr, hA, dnv, bC, N);
        // Pooling
        colsum_kernel<<<512, 256, 0, s0>>>(bC, colsump, N);
        gc_kernel<<<1, 64, 0, s0>>>(colsump, b2, att_w, gcp, 1.0f / (float)N);
        attpool_kernel<<<592, 256, 0, s0>>>(bC, b2, gcp, hp, N);
    }

    // ================= graph 1 (s1): CSR + aggregate-first phase ======
    {
        const int* src = ej;
        const int* dst = ej + E;
        int*   dg   = degp + MAXN;
        int*   off  = offp + (MAXN + 1);
        int*   cur  = curp + MAXN;
        int*   part = partp + 256;
        float* dnv  = dinvp + MAXN;
        int2*  csr  = csrp + (size_t)MAXE;
        float* bA = bufA + XCAP;
        float* bC = bufC + XCAP;
        __half* hA = (__half*)(bufB + XCAP);        // XCAP halves
        __half* hB = hA + XCAP;                      // XCAP halves

        // L2-heavy first: CSR build while s0 runs its L0 GEMM
        deg_kernel<<<eb256, 256, 0, s1>>>(dst, dg, E);
        scan1_kernel<<<scan_blocks, 1024, 0, s1>>>(dg, off, part, N);
        scan2_kernel<<<1, 128, 0, s1>>>(part, scan_blocks);
        scan3_kernel<<<nb256, 256, 0, s1>>>(off, part, cur, dg, dnv, N);
        scatter_kernel<<<eb256, 256, 0, s1>>>(src, dst, dnv, cur, csr, E);
        // L0 aggregate-first (64 cols: half the gather traffic), then GEMM
        agg_csr_kernel<float, 64><<<agg_blocks, 256, 0, s1>>>(off, csr, x_j, dnv, bC, N);
        gemm_kernel<float, 64, 128, false><<<gemm_blocks, dim3(32, 8), smem0, s1>>>(bC, w0, nullptr, hA, N);
        // L1 (input is fp16 L0 output)
        gemm_kernel<__half, 128, 128, true><<<gemm_blocks, dim3(32, 8), smem1, s1>>>(hA, w1, b0, hB, N);
        agg_csr_kernel<__half, 128><<<agg_blocks, 256, 0, s1>>>(off, csr, hB, dnv, bA, N);
        // L2
        gemm_kernel<float, 128, 64, true><<<gemm_blocks, dim3(16, 8), smem2, s1>>>(bA, w2, b1, hA, N);
        agg_csr_kernel<__half, 64><<<agg_blocks, 256, 0, s1>>>(off, csr, hA, dnv, bC, N);
        // Pooling
        colsum_kernel<<<512, 256, 0, s1>>>(bC, colsump + 64, N);
        gc_kernel<<<1, 64, 0, s1>>>(colsump + 64, b2, att_w, gcp + 64, 1.0f / (float)N);
        attpool_kernel<<<592, 256, 0, s1>>>(bC, b2, gcp + 64, hp + 64, N);
    }

    cudaEventRecord(g_evJoin, s1);
    cudaStreamWaitEvent(s0, g_evJoin, 0);

    final_kernel<<<1, 1024, 0, s0>>>(hp, ntn_wt, ntn_wm, ntn_b,
                                     mw0, mb0, mw1, mb1, mw2, mb2, mw3, mb3,
                                     sw, sb, out);
}

// round 13
// speedup vs baseline: 1.5067x; 1.2487x over previous
#include <cuda_runtime.h>
#include <cuda_fp16.h>
#include <math.h>
#include <mma.h>

// ---------------------------------------------------------------------------
// SimGNN on GB300: two anti-phased streams; fp16 activation storage; GEMMs on
// fp16 tensor cores (wmma m16n16k16, fp32 accumulate).
// ---------------------------------------------------------------------------

#define MAXN 100000
#define MAXE 1300000
#define XCAP ((size_t)MAXN * 128)

using namespace nvcuda;

__device__ __align__(16) float g_bufA[2 * XCAP];   // fp32 agg outputs / gemm inputs
__device__ __align__(16) float g_bufB[2 * XCAP];   // carved into fp16 xw buffers
__device__ __align__(16) float g_bufC[2 * XCAP];   // fp32 final agg / pooling input
__device__ __align__(16) float g_dinv[2 * MAXN];
__device__ __align__(16) int   g_deg [2 * MAXN];
__device__ __align__(16) int   g_off [2 * (MAXN + 1)];
__device__ __align__(16) int   g_cur [2 * MAXN];
__device__ __align__(16) int   g_part[2 * 256];
__device__ __align__(16) int2  g_csr [2 * (size_t)MAXE];
__device__ __align__(16) float g_colsum[2 * 64];
__device__ __align__(16) float g_gc[2 * 64];
__device__ __align__(16) float g_h[128];

static cudaStream_t g_s2;
static cudaEvent_t  g_evFork, g_evJoin;
namespace {
struct StreamInit {
    StreamInit() {
        cudaStreamCreateWithFlags(&g_s2, cudaStreamNonBlocking);
        cudaEventCreateWithFlags(&g_evFork, cudaEventDisableTiming);
        cudaEventCreateWithFlags(&g_evJoin, cudaEventDisableTiming);
    }
};
static StreamInit s_streamInit;
}

// ------------------------- type-generic loads/stores -----------------------
__device__ __forceinline__ float4 load4(const float* p) { return *(const float4*)p; }
__device__ __forceinline__ float4 load4(const __half* p) {
    const __half2* h = (const __half2*)p;
    float2 a = __half22float2(h[0]);
    float2 b = __half22float2(h[1]);
    return make_float4(a.x, a.y, b.x, b.y);
}
__device__ __forceinline__ float2 load2(const float* p) { return *(const float2*)p; }
__device__ __forceinline__ float2 load2(const __half* p) {
    return __half22float2(*(const __half2*)p);
}
__device__ __forceinline__ void store4h(__half* p, float4 v) {
    __half2* h = (__half2*)p;
    h[0] = __floats2half2_rn(v.x, v.y);
    h[1] = __floats2half2_rn(v.z, v.w);
}

// ---------------------------------------------------------------------------
__global__ void zero_all_kernel(int* __restrict__ deg, float* __restrict__ h,
                                float* __restrict__ colsum, int n2)
{
    int i = blockIdx.x * blockDim.x + threadIdx.x;
    if (i < n2) deg[i] = 0;
    if (i < 128) { h[i] = 0.f; colsum[i] = 0.f; }
}

__global__ void deg_kernel(const int* __restrict__ dst, int* __restrict__ deg, int E) {
    int i = blockIdx.x * blockDim.x + threadIdx.x;
    if (i < E) atomicAdd(&deg[dst[i]], 1);
}

// --------------------------- CSR build: scan ------------------------------
__global__ void scan1_kernel(const int* __restrict__ deg, int* __restrict__ off,
                             int* __restrict__ partials, int n)
{
    __shared__ int wsum[32];
    int gid  = blockIdx.x * 1024 + threadIdx.x;
    int lane = threadIdx.x & 31, wid = threadIdx.x >> 5;
    int v = (gid < n) ? deg[gid] : 0;
    int x = v;
#pragma unroll
    for (int o = 1; o < 32; o <<= 1) {
        int y = __shfl_up_sync(0xFFFFFFFFu, x, o);
        if (lane >= o) x += y;
    }
    if (lane == 31) wsum[wid] = x;
    __syncthreads();
    if (wid == 0) {
        int s = wsum[lane];
#pragma unroll
        for (int o = 1; o < 32; o <<= 1) {
            int y = __shfl_up_sync(0xFFFFFFFFu, s, o);
            if (lane >= o) s += y;
        }
        wsum[lane] = s;
    }
    __syncthreads();
    int excl = (wid > 0 ? wsum[wid - 1] : 0) + x - v;
    if (gid < n) off[gid] = excl;
    if (threadIdx.x == 1023) partials[blockIdx.x] = wsum[31];
}

__global__ void scan2_kernel(int* __restrict__ partials, int nb)
{
    __shared__ int wsum[4];
    int t = threadIdx.x;
    int lane = t & 31, w = t >> 5;
    int v = (t < nb) ? partials[t] : 0;
    int x = v;
#pragma unroll
    for (int o = 1; o < 32; o <<= 1) {
        int y = __shfl_up_sync(0xFFFFFFFFu, x, o);
        if (lane >= o) x += y;
    }
    if (lane == 31) wsum[w] = x;
    __syncthreads();
    if (w == 0 && lane < 4) {
        int s = wsum[lane];
#pragma unroll
        for (int o = 1; o < 4; o <<= 1) {
            int y = __shfl_up_sync(0x0000000Fu, s, o);
            if (lane >= o) s += y;
        }
        wsum[lane] = s;
    }
    __syncthreads();
    int incl = x + (w > 0 ? wsum[w - 1] : 0);
    if (t < nb) partials[t] = incl - v;
}

__global__ void scan3_kernel(int* __restrict__ off, const int* __restrict__ partials,
                             int* __restrict__ cur, const int* __restrict__ deg,
                             float* __restrict__ dinv, int n)
{
    int gid = blockIdx.x * blockDim.x + threadIdx.x;
    if (gid < n) {
        int o = off[gid] + partials[gid >> 10];
        off[gid] = o;
        cur[gid] = o;
        if (gid == n - 1) off[n] = o + deg[gid];
        dinv[gid] = rsqrtf((float)(deg[gid] + 1));
    }
}

__global__ void scatter_kernel(const int* __restrict__ src, const int* __restrict__ dst,
                               const float* __restrict__ dinv, int* __restrict__ cur,
                               int2* __restrict__ csr, int E)
{
    int e = blockIdx.x * blockDim.x + threadIdx.x;
    if (e >= E) return;
    int s = src[e], d = dst[e];
    int pos = atomicAdd(&cur[d], 1);
    csr[pos] = make_int2(s, __float_as_int(__ldg(&dinv[s])));
}

// ---------------------------------------------------------------------------
// fp16 tensor-core GEMM: xwH (fp16) = relu_fused(in) @ W.
// Block: 64 rows x DOUT, 256 threads (8 warps). Warp w: row-tile rt=w/2,
// col-tiles ctb=(w&1)*NT. wmma m16n16k16, fp16 inputs, fp32 accumulate.
// W converted fp32->fp16 into smem once; x staged fp16 with fused bias+relu.
template<typename TIN, int DIN, int DOUT, bool FUSE>
__global__ void __launch_bounds__(256)
gemm_kernel(const TIN* __restrict__ in, const float* __restrict__ W,
            const float* __restrict__ bprev, __half* __restrict__ xw, int n)
{
    constexpr int WS = DOUT + 16;    // half stride (32B-aligned tiles)
    constexpr int XS = DIN + 16;     // half stride
    constexpr int CT = DOUT / 16;    // col tiles
    constexpr int NT = CT / 2;       // col tiles per warp (4 or 2)

    extern __shared__ __half shh[];
    __half* Ws = shh;                           // DIN * WS halfs
    __half* xs = shh + DIN * WS;                // 64 * XS halfs
    float*  stage = (float*)(xs + 64 * XS);     // 8 * 256 floats

    const int tid  = threadIdx.x;
    const int w    = tid >> 5;
    const int lane = tid & 31;

    // W -> fp16 smem
    for (int i = tid; i < DIN * DOUT / 4; i += 256) {
        int row = i / (DOUT / 4), c4 = i % (DOUT / 4);
        float4 v = ((const float4*)(W + row * DOUT))[c4];
        __half2* d = (__half2*)(Ws + row * WS + c4 * 4);
        d[0] = __floats2half2_rn(v.x, v.y);
        d[1] = __floats2half2_rn(v.z, v.w);
    }

    // x tile (64 rows) -> fp16 smem with fused bias+relu, zero-pad OOB
    const int row0 = blockIdx.x * 64;
    for (int i = tid; i < 64 * DIN / 4; i += 256) {
        int r = i / (DIN / 4), kk = i % (DIN / 4);
        int row = row0 + r;
        float4 v = make_float4(0.f, 0.f, 0.f, 0.f);
        if (row < n) {
            v = load4(in + (size_t)row * DIN + kk * 4);
            if (FUSE) {
                float4 b = ((const float4*)bprev)[kk];
                v.x = fmaxf(v.x + b.x, 0.f);
                v.y = fmaxf(v.y + b.y, 0.f);
                v.z = fmaxf(v.z + b.z, 0.f);
                v.w = fmaxf(v.w + b.w, 0.f);
            }
        }
        __half2* d = (__half2*)(xs + r * XS + kk * 4);
        d[0] = __floats2half2_rn(v.x, v.y);
        d[1] = __floats2half2_rn(v.z, v.w);
    }
    __syncthreads();

    const int rt  = w >> 1;                 // row tile 0..3 (16 rows each)
    const int ctb = (w & 1) * NT;

    wmma::fragment<wmma::accumulator, 16, 16, 16, float> acc[NT];
#pragma unroll
    for (int t = 0; t < NT; t++) wmma::fill_fragment(acc[t], 0.f);

#pragma unroll
    for (int k0 = 0; k0 < DIN; k0 += 16) {
        wmma::fragment<wmma::matrix_a, 16, 16, 16, __half, wmma::row_major> a;
        wmma::load_matrix_sync(a, xs + rt * 16 * XS + k0, XS);
#pragma unroll
        for (int t = 0; t < NT; t++) {
            wmma::fragment<wmma::matrix_b, 16, 16, 16, __half, wmma::row_major> b;
            wmma::load_matrix_sync(b, Ws + k0 * WS + (ctb + t) * 16, WS);
            wmma::mma_sync(acc[t], a, b, acc[t]);
        }
    }

    // Store: stage fp32 in smem, convert to fp16, guarded half2 copies.
    const int trow = row0 + rt * 16;
    if (trow < n) {
        float* st = stage + w * 256;
#pragma unroll
        for (int t = 0; t < NT; t++) {
            wmma::store_matrix_sync(st, acc[t], 16, wmma::mem_row_major);
            __syncwarp();
#pragma unroll
            for (int q = 0; q < 4; q++) {
                int idx = lane + q * 32;          // half2 index 0..127
                int r = idx >> 3, c = (idx & 7) * 2;
                if (trow + r < n)
                    *(__half2*)(xw + (size_t)(trow + r) * DOUT + (ctb + t) * 16 + c) =
                        __floats2half2_rn(st[r * 16 + c], st[r * 16 + c + 1]);
            }
            __syncwarp();
        }
    }
}

// ---------------------------------------------------------------------------
// CSR aggregation (fp32 accumulate, TIN gather).
template<typename TIN, int DOUT>
__global__ void agg_csr_kernel(const int* __restrict__ off, const int2* __restrict__ csr,
                               const TIN* __restrict__ xw, const float* __restrict__ dinv,
                               float* __restrict__ aggout, int n)
{
    constexpr int VEC = DOUT / 32;   // 4 or 2
    int node = blockIdx.x * 8 + (threadIdx.x >> 5);
    if (node >= n) return;
    int lane = threadIdx.x & 31;

    float dv = __ldg(&dinv[node]);
    const TIN* xr = xw + (size_t)node * DOUT + lane * VEC;
    float acc[VEC], acc2[VEC];
    if (VEC == 4) {
        float4 v = load4(xr);
        acc[0] = v.x * dv * dv; acc[1] = v.y * dv * dv;
        acc[2] = v.z * dv * dv; acc[3] = v.w * dv * dv;
        acc2[0] = acc2[1] = acc2[2] = acc2[3] = 0.f;
    } else {
        float2 v = load2(xr);
        acc[0] = v.x * dv * dv; acc[1] = v.y * dv * dv;
        acc2[0] = acc2[1] = 0.f;
    }

    int p = __ldg(&off[node]);
    int pend = __ldg(&off[node + 1]);
    for (; p + 2 <= pend; p += 2) {
        int2 e0 = __ldg(&csr[p]);
        int2 e1 = __ldg(&csr[p + 1]);
        float n0 = __int_as_float(e0.y) * dv;
        float n1 = __int_as_float(e1.y) * dv;
        const TIN* s0 = xw + (size_t)e0.x * DOUT + lane * VEC;
        const TIN* s1 = xw + (size_t)e1.x * DOUT + lane * VEC;
        if (VEC == 4) {
            float4 v0 = load4(s0);
            float4 v1 = load4(s1);
            acc[0] = fmaf(n0, v0.x, acc[0]); acc[1] = fmaf(n0, v0.y, acc[1]);
            acc[2] = fmaf(n0, v0.z, acc[2]); acc[3] = fmaf(n0, v0.w, acc[3]);
            acc2[0] = fmaf(n1, v1.x, acc2[0]); acc2[1] = fmaf(n1, v1.y, acc2[1]);
            acc2[2] = fmaf(n1, v1.z, acc2[2]); acc2[3] = fmaf(n1, v1.w, acc2[3]);
        } else {
            float2 v0 = load2(s0);
            float2 v1 = load2(s1);
            acc[0] = fmaf(n0, v0.x, acc[0]); acc[1] = fmaf(n0, v0.y, acc[1]);
            acc2[0] = fmaf(n1, v1.x, acc2[0]); acc2[1] = fmaf(n1, v1.y, acc2[1]);
        }
    }
    if (p < pend) {
        int2 e0 = __ldg(&csr[p]);
        float n0 = __int_as_float(e0.y) * dv;
        const TIN* s0 = xw + (size_t)e0.x * DOUT + lane * VEC;
        if (VEC == 4) {
            float4 v0 = load4(s0);
            acc[0] = fmaf(n0, v0.x, acc[0]); acc[1] = fmaf(n0, v0.y, acc[1]);
            acc[2] = fmaf(n0, v0.z, acc[2]); acc[3] = fmaf(n0, v0.w, acc[3]);
        } else {
            float2 v0 = load2(s0);
            acc[0] = fmaf(n0, v0.x, acc[0]); acc[1] = fmaf(n0, v0.y, acc[1]);
        }
    }

    float* o = aggout + (size_t)node * DOUT + lane * VEC;
    if (VEC == 4)
        *(float4*)o = make_float4(acc[0] + acc2[0], acc[1] + acc2[1],
                                  acc[2] + acc2[2], acc[3] + acc2[3]);
    else
        *(float2*)o = make_float2(acc[0] + acc2[0], acc[1] + acc2[1]);
}

// ---------------------------------------------------------------------------
__global__ void colsum_kernel(const float* __restrict__ agg, float* __restrict__ colsum, int n)
{
    __shared__ float sm[256];
    int c  = threadIdx.x & 63;
    int rl = threadIdx.x >> 6;
    float acc = 0.f;
    for (int row = blockIdx.x * 4 + rl; row < n; row += gridDim.x * 4)
        acc += agg[(size_t)row * 64 + c];
    sm[threadIdx.x] = acc;
    __syncthreads();
    if (threadIdx.x < 64) {
        float s = sm[c] + sm[64 + c] + sm[128 + c] + sm[192 + c];
        atomicAdd(&colsum[c], s);
    }
}

__global__ void gc_kernel(const float* __restrict__ colsum, const float* __restrict__ b2,
                          const float* __restrict__ Wa, float* __restrict__ gc, float invN)
{
    __shared__ float mean[64];
    int t = threadIdx.x;
    mean[t] = colsum[t] * invN + b2[t];
    __syncthreads();
    float acc = 0.f;
#pragma unroll
    for (int d = 0; d < 64; d++) acc += mean[d] * Wa[d * 64 + t];
    gc[t] = tanhf(acc);
}

__global__ void attpool_kernel(const float* __restrict__ agg, const float* __restrict__ b2,
                               const float* __restrict__ gc, float* __restrict__ h, int n)
{
    __shared__ float gcs[64], b2s[64];
    __shared__ float red[8][64];
    int tid = threadIdx.x;
    if (tid < 64) { gcs[tid] = gc[tid]; b2s[tid] = b2[tid]; }
    __syncthreads();
    int lane = tid & 31, w = tid >> 5;
    float gx = gcs[2 * lane], gy = gcs[2 * lane + 1];
    float bx = b2s[2 * lane], by = b2s[2 * lane + 1];
    float ax = 0.f, ay = 0.f;
    for (int row = blockIdx.x * 8 + w; row < n; row += gridDim.x * 8) {
        float2 v = *(const float2*)(agg + (size_t)row * 64 + 2 * lane);
        v.x += bx; v.y += by;
        float d = v.x * gx + v.y * gy;
#pragma unroll
        for (int o = 16; o; o >>= 1) d += __shfl_xor_sync(0xFFFFFFFFu, d, o);
        float att = 1.f / (1.f + expf(-d));
        ax += v.x * att; ay += v.y * att;
    }
    red[w][2 * lane] = ax; red[w][2 * lane + 1] = ay;
    __syncthreads();
    if (w == 0) {
        float sx = 0.f, sy = 0.f;
#pragma unroll
        for (int i = 0; i < 8; i++) { sx += red[i][2 * lane]; sy += red[i][2 * lane + 1]; }
        atomicAdd(&h[2 * lane], sx);
        atomicAdd(&h[2 * lane + 1], sy);
    }
}

// ---------------------------------------------------------------------------
__global__ void final_kernel(const float* __restrict__ h,
                             const float* __restrict__ Wt, const float* __restrict__ Wm,
                             const float* __restrict__ nb,
                             const float* __restrict__ w0, const float* __restrict__ bb0,
                             const float* __restrict__ w1, const float* __restrict__ bb1,
                             const float* __restrict__ w2, const float* __restrict__ bb2,
                             const float* __restrict__ w3, const float* __restrict__ bb3,
                             const float* __restrict__ sw, const float* __restrict__ sb,
                             float* __restrict__ out)
{
    __shared__ float hi[64], hj[64];
    __shared__ float part[1024];
    __shared__ float z[16];
    int t = threadIdx.x;
    if (t < 64) hi[t] = h[t];
    else if (t < 128) hj[t - 64] = h[t];
    __syncthreads();

    int k = t >> 6, e = t & 63;
    const float* wt = Wt + (size_t)k * 4096 + e;
    float acc = 0.f;
#pragma unroll
    for (int d = 0; d < 64; d++) acc += hi[d] * wt[d * 64];
    part[t] = acc * hj[e];
    __syncthreads();

    if (t < 16) {
        float s = 0.f;
        for (int e2 = 0; e2 < 64; e2++) s += part[t * 64 + e2];
        float lin = 0.f;
        const float* wm = Wm + t * 128;
        for (int m = 0; m < 64; m++) lin += wm[m] * hi[m] + wm[64 + m] * hj[m];
        z[t] = tanhf(s + lin + nb[t]);
    }
    __syncthreads();

    if (t == 0) {
        float a[32], b[32];
        for (int j = 0; j < 32; j++) { float s = bb0[j]; for (int i = 0; i < 16; i++) s += z[i] * w0[i * 32 + j]; a[j] = fmaxf(s, 0.f); }
        for (int j = 0; j < 16; j++) { float s = bb1[j]; for (int i = 0; i < 32; i++) s += a[i] * w1[i * 16 + j]; b[j] = fmaxf(s, 0.f); }
        for (int j = 0; j <  8; j++) { float s = bb2[j]; for (int i = 0; i < 16; i++) s += b[i] * w2[i * 8 + j];  a[j] = fmaxf(s, 0.f); }
        for (int j = 0; j <  4; j++) { float s = bb3[j]; for (int i = 0; i <  8; i++) s += a[i] * w3[i * 4 + j];  b[j] = fmaxf(s, 0.f); }
        float s = sb[0];
        for (int i = 0; i < 4; i++) s += b[i] * sw[i];
        out[0] = s;
    }
}

// ---------------------------------------------------------------------------
extern "C" void kernel_launch(void* const* d_in, const int* in_sizes, int n_in,
                              void* d_out, int out_size)
{
    const float* x_i = (const float*)d_in[0];
    const int*   ei  = (const int*)d_in[1];     // int32 (JAX x64 disabled)
    const float* x_j = (const float*)d_in[2];
    const int*   ej  = (const int*)d_in[3];
    const float* w0 = (const float*)d_in[4];
    const float* b0 = (const float*)d_in[5];
    const float* w1 = (const float*)d_in[6];
    const float* b1 = (const float*)d_in[7];
    const float* w2 = (const float*)d_in[8];
    const float* b2 = (const float*)d_in[9];
    const float* att_w  = (const float*)d_in[10];
    const float* ntn_wt = (const float*)d_in[11];
    const float* ntn_wm = (const float*)d_in[12];
    const float* ntn_b  = (const float*)d_in[13];
    const float* mw0 = (const float*)d_in[14];
    const float* mb0 = (const float*)d_in[15];
    const float* mw1 = (const float*)d_in[16];
    const float* mb1 = (const float*)d_in[17];
    const float* mw2 = (const float*)d_in[18];
    const float* mb2 = (const float*)d_in[19];
    const float* mw3 = (const float*)d_in[20];
    const float* mb3 = (const float*)d_in[21];
    const float* sw  = (const float*)d_in[22];
    const float* sb  = (const float*)d_in[23];
    float* out = (float*)d_out;

    const int N = in_sizes[0] / 64;
    const int E = in_sizes[1] / 2;

    float *bufA, *bufB, *bufC, *dinvp, *colsump, *gcp, *hp;
    int *degp, *offp, *curp, *partp;
    int2* csrp;
    cudaGetSymbolAddress((void**)&bufA,    g_bufA);
    cudaGetSymbolAddress((void**)&bufB,    g_bufB);
    cudaGetSymbolAddress((void**)&bufC,    g_bufC);
    cudaGetSymbolAddress((void**)&dinvp,   g_dinv);
    cudaGetSymbolAddress((void**)&degp,    g_deg);
    cudaGetSymbolAddress((void**)&offp,    g_off);
    cudaGetSymbolAddress((void**)&curp,    g_cur);
    cudaGetSymbolAddress((void**)&partp,   g_part);
    cudaGetSymbolAddress((void**)&csrp,    g_csr);
    cudaGetSymbolAddress((void**)&colsump, g_colsum);
    cudaGetSymbolAddress((void**)&gcp,     g_gc);
    cudaGetSymbolAddress((void**)&hp,      g_h);

    // smem (halfs): W DIN*(DOUT+16) + x 64*(DIN+16), plus 8*256 floats stage
    const int smem0 = (64  * 144 + 64 * 80 ) * 2 + 8192;   // 36864+ -> 36.9KB
    const int smem1 = (128 * 144 + 64 * 144) * 2 + 8192;   // 63.5KB
    const int smem2 = (128 * 80  + 64 * 144) * 2 + 8192;   // 47.1KB
    cudaFuncSetAttribute(gemm_kernel<float, 64, 128, false>, cudaFuncAttributeMaxDynamicSharedMemorySize, smem0);
    cudaFuncSetAttribute(gemm_kernel<float, 128, 128, true>, cudaFuncAttributeMaxDynamicSharedMemorySize, smem1);
    cudaFuncSetAttribute(gemm_kernel<__half, 128, 128, true>, cudaFuncAttributeMaxDynamicSharedMemorySize, smem1);
    cudaFuncSetAttribute(gemm_kernel<float, 128, 64,  true>, cudaFuncAttributeMaxDynamicSharedMemorySize, smem2);

    const int gemm_blocks = (N + 63) / 64;
    const int agg_blocks  = (N + 7) / 8;
    const int scan_blocks = (N + 1023) / 1024;
    const int nb256 = (N + 255) / 256;
    const int eb256 = (E + 255) / 256;

    cudaStream_t s0 = 0;          // captured legacy stream (graph 0)
    cudaStream_t s1 = g_s2;       // forked stream (graph 1)

    zero_all_kernel<<<(2 * N + 255) / 256, 256, 0, s0>>>(degp, hp, colsump, 2 * N);
    cudaEventRecord(g_evFork, s0);
    cudaStreamWaitEvent(s1, g_evFork, 0);

    // ================= graph 0 (s0): GEMM-first phase =================
    {
        const int* src = ei;
        const int* dst = ei + E;
        int*   dg   = degp;
        int*   off  = offp;
        int*   cur  = curp;
        int*   part = partp;
        float* dnv  = dinvp;
        int2*  csr  = csrp;
        float* bA = bufA;
        float* bC = bufC;
        __half* hA = (__half*)bufB;

        gemm_kernel<float, 64, 128, false><<<gemm_blocks, 256, smem0, s0>>>(x_i, w0, nullptr, hA, N);
        deg_kernel<<<eb256, 256, 0, s0>>>(dst, dg, E);
        scan1_kernel<<<scan_blocks, 1024, 0, s0>>>(dg, off, part, N);
        scan2_kernel<<<1, 128, 0, s0>>>(part, scan_blocks);
        scan3_kernel<<<nb256, 256, 0, s0>>>(off, part, cur, dg, dnv, N);
        scatter_kernel<<<eb256, 256, 0, s0>>>(src, dst, dnv, cur, csr, E);
        agg_csr_kernel<__half, 128><<<agg_blocks, 256, 0, s0>>>(off, csr, hA, dnv, bA, N);
        gemm_kernel<float, 128, 128, true><<<gemm_blocks, 256, smem1, s0>>>(bA, w1, b0, hA, N);
        agg_csr_kernel<__half, 128><<<agg_blocks, 256, 0, s0>>>(off, csr, hA, dnv, bA, N);
        gemm_kernel<float, 128, 64, true><<<gemm_blocks, 256, smem2, s0>>>(bA, w2, b1, hA, N);
        agg_csr_kernel<__half, 64><<<agg_blocks, 256, 0, s0>>>(off, csr, hA, dnv, bC, N);
        colsum_kernel<<<512, 256, 0, s0>>>(bC, colsump, N);
        gc_kernel<<<1, 64, 0, s0>>>(colsump, b2, att_w, gcp, 1.0f / (float)N);
        attpool_kernel<<<592, 256, 0, s0>>>(bC, b2, gcp, hp, N);
    }

    // ================= graph 1 (s1): CSR + aggregate-first phase ======
    {
        const int* src = ej;
        const int* dst = ej + E;
        int*   dg   = degp + MAXN;
        int*   off  = offp + (MAXN + 1);
        int*   cur  = curp + MAXN;
        int*   part = partp + 256;
        float* dnv  = dinvp + MAXN;
        int2*  csr  = csrp + (size_t)MAXE;
        float* bA = bufA + XCAP;
        float* bC = bufC + XCAP;
        __half* hA = (__half*)(bufB + XCAP);
        __half* hB = hA + XCAP;

        deg_kernel<<<eb256, 256, 0, s1>>>(dst, dg, E);
        scan1_kernel<<<scan_blocks, 1024, 0, s1>>>(dg, off, part, N);
        scan2_kernel<<<1, 128, 0, s1>>>(part, scan_blocks);
        scan3_kernel<<<nb256, 256, 0, s1>>>(off, part, cur, dg, dnv, N);
        scatter_kernel<<<eb256, 256, 0, s1>>>(src, dst, dnv, cur, csr, E);
        agg_csr_kernel<float, 64><<<agg_blocks, 256, 0, s1>>>(off, csr, x_j, dnv, bC, N);
        gemm_kernel<float, 64, 128, false><<<gemm_blocks, 256, smem0, s1>>>(bC, w0, nullptr, hA, N);
        gemm_kernel<__half, 128, 128, true><<<gemm_blocks, 256, smem1, s1>>>(hA, w1, b0, hB, N);
        agg_csr_kernel<__half, 128><<<agg_blocks, 256, 0, s1>>>(off, csr, hB, dnv, bA, N);
        gemm_kernel<float, 128, 64, true><<<gemm_blocks, 256, smem2, s1>>>(bA, w2, b1, hA, N);
        agg_csr_kernel<__half, 64><<<agg_blocks, 256, 0, s1>>>(off, csr, hA, dnv, bC, N);
        colsum_kernel<<<512, 256, 0, s1>>>(bC, colsump + 64, N);
        gc_kernel<<<1, 64, 0, s1>>>(colsump + 64, b2, att_w, gcp + 64, 1.0f / (float)N);
        attpool_kernel<<<592, 256, 0, s1>>>(bC, b2, gcp + 64, hp + 64, N);
    }

    cudaEventRecord(g_evJoin, s1);
    cudaStreamWaitEvent(s0, g_evJoin, 0);

    final_kernel<<<1, 1024, 0, s0>>>(hp, ntn_wt, ntn_wm, ntn_b,
                                     mw0, mb0, mw1, mb1, mw2, mb2, mw3, mb3,
                                     sw, sb, out);
}

// round 14
// speedup vs baseline: 1.5433x; 1.0243x over previous
#include <cuda_runtime.h>
#include <cuda_fp16.h>
#include <math.h>
#include <mma.h>

// ---------------------------------------------------------------------------
// SimGNN on GB300: two anti-phased streams; fp16 activation storage everywhere
// between GEMMs and aggregations (math fp32); fp16 tensor-core GEMMs.
// ---------------------------------------------------------------------------

#define MAXN 100000
#define MAXE 1300000
#define XCAP ((size_t)MAXN * 128)

using namespace nvcuda;

__device__ __align__(16) float g_bufA[2 * XCAP];   // carved: fp16 agg outputs
__device__ __align__(16) float g_bufB[2 * XCAP];   // carved: fp16 gemm outputs
__device__ __align__(16) float g_bufC[2 * XCAP];   // fp32 final agg / pooling input
__device__ __align__(16) float g_dinv[2 * MAXN];
__device__ __align__(16) int   g_deg [2 * MAXN];
__device__ __align__(16) int   g_off [2 * (MAXN + 1)];
__device__ __align__(16) int   g_cur [2 * MAXN];
__device__ __align__(16) int   g_part[2 * 256];
__device__ __align__(16) int2  g_csr [2 * (size_t)MAXE];
__device__ __align__(16) float g_colsum[2 * 64];
__device__ __align__(16) float g_gc[2 * 64];
__device__ __align__(16) float g_h[128];

static cudaStream_t g_s2;
static cudaEvent_t  g_evFork, g_evJoin;
namespace {
struct StreamInit {
    StreamInit() {
        cudaStreamCreateWithFlags(&g_s2, cudaStreamNonBlocking);
        cudaEventCreateWithFlags(&g_evFork, cudaEventDisableTiming);
        cudaEventCreateWithFlags(&g_evJoin, cudaEventDisableTiming);
    }
};
static StreamInit s_streamInit;
}

// ------------------------- type-generic loads/stores -----------------------
__device__ __forceinline__ float4 load4(const float* p) { return *(const float4*)p; }
__device__ __forceinline__ float4 load4(const __half* p) {
    const __half2* h = (const __half2*)p;
    float2 a = __half22float2(h[0]);
    float2 b = __half22float2(h[1]);
    return make_float4(a.x, a.y, b.x, b.y);
}
__device__ __forceinline__ float2 load2(const float* p) { return *(const float2*)p; }
__device__ __forceinline__ float2 load2(const __half* p) {
    return __half22float2(*(const __half2*)p);
}
__device__ __forceinline__ void store4(float* p, float4 v) { *(float4*)p = v; }
__device__ __forceinline__ void store4(__half* p, float4 v) {
    __half2* h = (__half2*)p;
    h[0] = __floats2half2_rn(v.x, v.y);
    h[1] = __floats2half2_rn(v.z, v.w);
}
__device__ __forceinline__ void store2(float* p, float2 v) { *(float2*)p = v; }
__device__ __forceinline__ void store2(__half* p, float2 v) {
    *(__half2*)p = __floats2half2_rn(v.x, v.y);
}

// ---------------------------------------------------------------------------
__global__ void zero_all_kernel(int* __restrict__ deg, float* __restrict__ h,
                                float* __restrict__ colsum, int n2)
{
    int i = blockIdx.x * blockDim.x + threadIdx.x;
    if (i < n2) deg[i] = 0;
    if (i < 128) { h[i] = 0.f; colsum[i] = 0.f; }
}

__global__ void deg_kernel(const int* __restrict__ dst, int* __restrict__ deg, int E) {
    int i = blockIdx.x * blockDim.x + threadIdx.x;
    if (i < E) atomicAdd(&deg[dst[i]], 1);
}

// --------------------------- CSR build: scan ------------------------------
__global__ void scan1_kernel(const int* __restrict__ deg, int* __restrict__ off,
                             int* __restrict__ partials, int n)
{
    __shared__ int wsum[32];
    int gid  = blockIdx.x * 1024 + threadIdx.x;
    int lane = threadIdx.x & 31, wid = threadIdx.x >> 5;
    int v = (gid < n) ? deg[gid] : 0;
    int x = v;
#pragma unroll
    for (int o = 1; o < 32; o <<= 1) {
        int y = __shfl_up_sync(0xFFFFFFFFu, x, o);
        if (lane >= o) x += y;
    }
    if (lane == 31) wsum[wid] = x;
    __syncthreads();
    if (wid == 0) {
        int s = wsum[lane];
#pragma unroll
        for (int o = 1; o < 32; o <<= 1) {
            int y = __shfl_up_sync(0xFFFFFFFFu, s, o);
            if (lane >= o) s += y;
        }
        wsum[lane] = s;
    }
    __syncthreads();
    int excl = (wid > 0 ? wsum[wid - 1] : 0) + x - v;
    if (gid < n) off[gid] = excl;
    if (threadIdx.x == 1023) partials[blockIdx.x] = wsum[31];
}

__global__ void scan2_kernel(int* __restrict__ partials, int nb)
{
    __shared__ int wsum[4];
    int t = threadIdx.x;
    int lane = t & 31, w = t >> 5;
    int v = (t < nb) ? partials[t] : 0;
    int x = v;
#pragma unroll
    for (int o = 1; o < 32; o <<= 1) {
        int y = __shfl_up_sync(0xFFFFFFFFu, x, o);
        if (lane >= o) x += y;
    }
    if (lane == 31) wsum[w] = x;
    __syncthreads();
    if (w == 0 && lane < 4) {
        int s = wsum[lane];
#pragma unroll
        for (int o = 1; o < 4; o <<= 1) {
            int y = __shfl_up_sync(0x0000000Fu, s, o);
            if (lane >= o) s += y;
        }
        wsum[lane] = s;
    }
    __syncthreads();
    int incl = x + (w > 0 ? wsum[w - 1] : 0);
    if (t < nb) partials[t] = incl - v;
}

__global__ void scan3_kernel(int* __restrict__ off, const int* __restrict__ partials,
                             int* __restrict__ cur, const int* __restrict__ deg,
                             float* __restrict__ dinv, int n)
{
    int gid = blockIdx.x * blockDim.x + threadIdx.x;
    if (gid < n) {
        int o = off[gid] + partials[gid >> 10];
        off[gid] = o;
        cur[gid] = o;
        if (gid == n - 1) off[n] = o + deg[gid];
        dinv[gid] = rsqrtf((float)(deg[gid] + 1));
    }
}

__global__ void scatter_kernel(const int* __restrict__ src, const int* __restrict__ dst,
                               const float* __restrict__ dinv, int* __restrict__ cur,
                               int2* __restrict__ csr, int E)
{
    int e = blockIdx.x * blockDim.x + threadIdx.x;
    if (e >= E) return;
    int s = src[e], d = dst[e];
    int pos = atomicAdd(&cur[d], 1);
    csr[pos] = make_int2(s, __float_as_int(__ldg(&dinv[s])));
}

// ---------------------------------------------------------------------------
// fp16 tensor-core GEMM: xwH (fp16) = relu_fused(in) @ W. (R13-proven)
template<typename TIN, int DIN, int DOUT, bool FUSE>
__global__ void __launch_bounds__(256)
gemm_kernel(const TIN* __restrict__ in, const float* __restrict__ W,
            const float* __restrict__ bprev, __half* __restrict__ xw, int n)
{
    constexpr int WS = DOUT + 16;
    constexpr int XS = DIN + 16;
    constexpr int CT = DOUT / 16;
    constexpr int NT = CT / 2;

    extern __shared__ __half shh[];
    __half* Ws = shh;                           // DIN * WS halfs
    __half* xs = shh + DIN * WS;                // 64 * XS halfs
    float*  stage = (float*)(xs + 64 * XS);     // 8 * 256 floats

    const int tid  = threadIdx.x;
    const int w    = tid >> 5;
    const int lane = tid & 31;

    for (int i = tid; i < DIN * DOUT / 4; i += 256) {
        int row = i / (DOUT / 4), c4 = i % (DOUT / 4);
        float4 v = ((const float4*)(W + row * DOUT))[c4];
        __half2* d = (__half2*)(Ws + row * WS + c4 * 4);
        d[0] = __floats2half2_rn(v.x, v.y);
        d[1] = __floats2half2_rn(v.z, v.w);
    }

    const int row0 = blockIdx.x * 64;
    for (int i = tid; i < 64 * DIN / 4; i += 256) {
        int r = i / (DIN / 4), kk = i % (DIN / 4);
        int row = row0 + r;
        float4 v = make_float4(0.f, 0.f, 0.f, 0.f);
        if (row < n) {
            v = load4(in + (size_t)row * DIN + kk * 4);
            if (FUSE) {
                float4 b = ((const float4*)bprev)[kk];
                v.x = fmaxf(v.x + b.x, 0.f);
                v.y = fmaxf(v.y + b.y, 0.f);
                v.z = fmaxf(v.z + b.z, 0.f);
                v.w = fmaxf(v.w + b.w, 0.f);
            }
        }
        __half2* d = (__half2*)(xs + r * XS + kk * 4);
        d[0] = __floats2half2_rn(v.x, v.y);
        d[1] = __floats2half2_rn(v.z, v.w);
    }
    __syncthreads();

    const int rt  = w >> 1;
    const int ctb = (w & 1) * NT;

    wmma::fragment<wmma::accumulator, 16, 16, 16, float> acc[NT];
#pragma unroll
    for (int t = 0; t < NT; t++) wmma::fill_fragment(acc[t], 0.f);

#pragma unroll
    for (int k0 = 0; k0 < DIN; k0 += 16) {
        wmma::fragment<wmma::matrix_a, 16, 16, 16, __half, wmma::row_major> a;
        wmma::load_matrix_sync(a, xs + rt * 16 * XS + k0, XS);
#pragma unroll
        for (int t = 0; t < NT; t++) {
            wmma::fragment<wmma::matrix_b, 16, 16, 16, __half, wmma::row_major> b;
            wmma::load_matrix_sync(b, Ws + k0 * WS + (ctb + t) * 16, WS);
            wmma::mma_sync(acc[t], a, b, acc[t]);
        }
    }

    const int trow = row0 + rt * 16;
    if (trow < n) {
        float* st = stage + w * 256;
#pragma unroll
        for (int t = 0; t < NT; t++) {
            wmma::store_matrix_sync(st, acc[t], 16, wmma::mem_row_major);
            __syncwarp();
#pragma unroll
            for (int q = 0; q < 4; q++) {
                int idx = lane + q * 32;
                int r = idx >> 3, c = (idx & 7) * 2;
                if (trow + r < n)
                    *(__half2*)(xw + (size_t)(trow + r) * DOUT + (ctb + t) * 16 + c) =
                        __floats2half2_rn(st[r * 16 + c], st[r * 16 + c + 1]);
            }
            __syncwarp();
        }
    }
}

// ---------------------------------------------------------------------------
// CSR aggregation (fp32 accumulate, TIN gather, TOUT store).
template<typename TIN, typename TOUT, int DOUT>
__global__ void agg_csr_kernel(const int* __restrict__ off, const int2* __restrict__ csr,
                               const TIN* __restrict__ xw, const float* __restrict__ dinv,
                               TOUT* __restrict__ aggout, int n)
{
    constexpr int VEC = DOUT / 32;   // 4 or 2
    int node = blockIdx.x * 8 + (threadIdx.x >> 5);
    if (node >= n) return;
    int lane = threadIdx.x & 31;

    float dv = __ldg(&dinv[node]);
    const TIN* xr = xw + (size_t)node * DOUT + lane * VEC;
    float acc[VEC], acc2[VEC];
    if (VEC == 4) {
        float4 v = load4(xr);
        acc[0] = v.x * dv * dv; acc[1] = v.y * dv * dv;
        acc[2] = v.z * dv * dv; acc[3] = v.w * dv * dv;
        acc2[0] = acc2[1] = acc2[2] = acc2[3] = 0.f;
    } else {
        float2 v = load2(xr);
        acc[0] = v.x * dv * dv; acc[1] = v.y * dv * dv;
        acc2[0] = acc2[1] = 0.f;
    }

    int p = __ldg(&off[node]);
    int pend = __ldg(&off[node + 1]);
    for (; p + 2 <= pend; p += 2) {
        int2 e0 = __ldg(&csr[p]);
        int2 e1 = __ldg(&csr[p + 1]);
        float n0 = __int_as_float(e0.y) * dv;
        float n1 = __int_as_float(e1.y) * dv;
        const TIN* s0 = xw + (size_t)e0.x * DOUT + lane * VEC;
        const TIN* s1 = xw + (size_t)e1.x * DOUT + lane * VEC;
        if (VEC == 4) {
            float4 v0 = load4(s0);
            float4 v1 = load4(s1);
            acc[0] = fmaf(n0, v0.x, acc[0]); acc[1] = fmaf(n0, v0.y, acc[1]);
            acc[2] = fmaf(n0, v0.z, acc[2]); acc[3] = fmaf(n0, v0.w, acc[3]);
            acc2[0] = fmaf(n1, v1.x, acc2[0]); acc2[1] = fmaf(n1, v1.y, acc2[1]);
            acc2[2] = fmaf(n1, v1.z, acc2[2]); acc2[3] = fmaf(n1, v1.w, acc2[3]);
        } else {
            float2 v0 = load2(s0);
            float2 v1 = load2(s1);
            acc[0] = fmaf(n0, v0.x, acc[0]); acc[1] = fmaf(n0, v0.y, acc[1]);
            acc2[0] = fmaf(n1, v1.x, acc2[0]); acc2[1] = fmaf(n1, v1.y, acc2[1]);
        }
    }
    if (p < pend) {
        int2 e0 = __ldg(&csr[p]);
        float n0 = __int_as_float(e0.y) * dv;
        const TIN* s0 = xw + (size_t)e0.x * DOUT + lane * VEC;
        if (VEC == 4) {
            float4 v0 = load4(s0);
            acc[0] = fmaf(n0, v0.x, acc[0]); acc[1] = fmaf(n0, v0.y, acc[1]);
            acc[2] = fmaf(n0, v0.z, acc[2]); acc[3] = fmaf(n0, v0.w, acc[3]);
        } else {
            float2 v0 = load2(s0);
            acc[0] = fmaf(n0, v0.x, acc[0]); acc[1] = fmaf(n0, v0.y, acc[1]);
        }
    }

    TOUT* o = aggout + (size_t)node * DOUT + lane * VEC;
    if (VEC == 4)
        store4(o, make_float4(acc[0] + acc2[0], acc[1] + acc2[1],
                              acc[2] + acc2[2], acc[3] + acc2[3]));
    else
        store2(o, make_float2(acc[0] + acc2[0], acc[1] + acc2[1]));
}

// ---------------------------------------------------------------------------
__global__ void colsum_kernel(const float* __restrict__ agg, float* __restrict__ colsum, int n)
{
    __shared__ float sm[256];
    int c  = threadIdx.x & 63;
    int rl = threadIdx.x >> 6;
    float acc = 0.f;
    for (int row = blockIdx.x * 4 + rl; row < n; row += gridDim.x * 4)
        acc += agg[(size_t)row * 64 + c];
    sm[threadIdx.x] = acc;
    __syncthreads();
    if (threadIdx.x < 64) {
        float s = sm[c] + sm[64 + c] + sm[128 + c] + sm[192 + c];
        atomicAdd(&colsum[c], s);
    }
}

__global__ void gc_kernel(const float* __restrict__ colsum, const float* __restrict__ b2,
                          const float* __restrict__ Wa, float* __restrict__ gc, float invN)
{
    __shared__ float mean[64];
    int t = threadIdx.x;
    mean[t] = colsum[t] * invN + b2[t];
    __syncthreads();
    float acc = 0.f;
#pragma unroll
    for (int d = 0; d < 64; d++) acc += mean[d] * Wa[d * 64 + t];
    gc[t] = tanhf(acc);
}

__global__ void attpool_kernel(const float* __restrict__ agg, const float* __restrict__ b2,
                               const float* __restrict__ gc, float* __restrict__ h, int n)
{
    __shared__ float gcs[64], b2s[64];
    __shared__ float red[8][64];
    int tid = threadIdx.x;
    if (tid < 64) { gcs[tid] = gc[tid]; b2s[tid] = b2[tid]; }
    __syncthreads();
    int lane = tid & 31, w = tid >> 5;
    float gx = gcs[2 * lane], gy = gcs[2 * lane + 1];
    float bx = b2s[2 * lane], by = b2s[2 * lane + 1];
    float ax = 0.f, ay = 0.f;
    for (int row = blockIdx.x * 8 + w; row < n; row += gridDim.x * 8) {
        float2 v = *(const float2*)(agg + (size_t)row * 64 + 2 * lane);
        v.x += bx; v.y += by;
        float d = v.x * gx + v.y * gy;
#pragma unroll
        for (int o = 16; o; o >>= 1) d += __shfl_xor_sync(0xFFFFFFFFu, d, o);
        float att = 1.f / (1.f + expf(-d));
        ax += v.x * att; ay += v.y * att;
    }
    red[w][2 * lane] = ax; red[w][2 * lane + 1] = ay;
    __syncthreads();
    if (w == 0) {
        float sx = 0.f, sy = 0.f;
#pragma unroll
        for (int i = 0; i < 8; i++) { sx += red[i][2 * lane]; sy += red[i][2 * lane + 1]; }
        atomicAdd(&h[2 * lane], sx);
        atomicAdd(&h[2 * lane + 1], sy);
    }
}

// ---------------------------------------------------------------------------
__global__ void final_kernel(const float* __restrict__ h,
                             const float* __restrict__ Wt, const float* __restrict__ Wm,
                             const float* __restrict__ nb,
                             const float* __restrict__ w0, const float* __restrict__ bb0,
                             const float* __restrict__ w1, const float* __restrict__ bb1,
                             const float* __restrict__ w2, const float* __restrict__ bb2,
                             const float* __restrict__ w3, const float* __restrict__ bb3,
                             const float* __restrict__ sw, const float* __restrict__ sb,
                             float* __restrict__ out)
{
    __shared__ float hi[64], hj[64];
    __shared__ float part[1024];
    __shared__ float z[16];
    int t = threadIdx.x;
    if (t < 64) hi[t] = h[t];
    else if (t < 128) hj[t - 64] = h[t];
    __syncthreads();

    int k = t >> 6, e = t & 63;
    const float* wt = Wt + (size_t)k * 4096 + e;
    float acc = 0.f;
#pragma unroll
    for (int d = 0; d < 64; d++) acc += hi[d] * wt[d * 64];
    part[t] = acc * hj[e];
    __syncthreads();

    if (t < 16) {
        float s = 0.f;
        for (int e2 = 0; e2 < 64; e2++) s += part[t * 64 + e2];
        float lin = 0.f;
        const float* wm = Wm + t * 128;
        for (int m = 0; m < 64; m++) lin += wm[m] * hi[m] + wm[64 + m] * hj[m];
        z[t] = tanhf(s + lin + nb[t]);
    }
    __syncthreads();

    if (t == 0) {
        float a[32], b[32];
        for (int j = 0; j < 32; j++) { float s = bb0[j]; for (int i = 0; i < 16; i++) s += z[i] * w0[i * 32 + j]; a[j] = fmaxf(s, 0.f); }
        for (int j = 0; j < 16; j++) { float s = bb1[j]; for (int i = 0; i < 32; i++) s += a[i] * w1[i * 16 + j]; b[j] = fmaxf(s, 0.f); }
        for (int j = 0; j <  8; j++) { float s = bb2[j]; for (int i = 0; i < 16; i++) s += b[i] * w2[i * 8 + j];  a[j] = fmaxf(s, 0.f); }
        for (int j = 0; j <  4; j++) { float s = bb3[j]; for (int i = 0; i <  8; i++) s += a[i] * w3[i * 4 + j];  b[j] = fmaxf(s, 0.f); }
        float s = sb[0];
        for (int i = 0; i < 4; i++) s += b[i] * sw[i];
        out[0] = s;
    }
}

// ---------------------------------------------------------------------------
extern "C" void kernel_launch(void* const* d_in, const int* in_sizes, int n_in,
                              void* d_out, int out_size)
{
    const float* x_i = (const float*)d_in[0];
    const int*   ei  = (const int*)d_in[1];     // int32 (JAX x64 disabled)
    const float* x_j = (const float*)d_in[2];
    const int*   ej  = (const int*)d_in[3];
    const float* w0 = (const float*)d_in[4];
    const float* b0 = (const float*)d_in[5];
    const float* w1 = (const float*)d_in[6];
    const float* b1 = (const float*)d_in[7];
    const float* w2 = (const float*)d_in[8];
    const float* b2 = (const float*)d_in[9];
    const float* att_w  = (const float*)d_in[10];
    const float* ntn_wt = (const float*)d_in[11];
    const float* ntn_wm = (const float*)d_in[12];
    const float* ntn_b  = (const float*)d_in[13];
    const float* mw0 = (const float*)d_in[14];
    const float* mb0 = (const float*)d_in[15];
    const float* mw1 = (const float*)d_in[16];
    const float* mb1 = (const float*)d_in[17];
    const float* mw2 = (const float*)d_in[18];
    const float* mb2 = (const float*)d_in[19];
    const float* mw3 = (const float*)d_in[20];
    const float* mb3 = (const float*)d_in[21];
    const float* sw  = (const float*)d_in[22];
    const float* sb  = (const float*)d_in[23];
    float* out = (float*)d_out;

    const int N = in_sizes[0] / 64;
    const int E = in_sizes[1] / 2;

    float *bufA, *bufB, *bufC, *dinvp, *colsump, *gcp, *hp;
    int *degp, *offp, *curp, *partp;
    int2* csrp;
    cudaGetSymbolAddress((void**)&bufA,    g_bufA);
    cudaGetSymbolAddress((void**)&bufB,    g_bufB);
    cudaGetSymbolAddress((void**)&bufC,    g_bufC);
    cudaGetSymbolAddress((void**)&dinvp,   g_dinv);
    cudaGetSymbolAddress((void**)&degp,    g_deg);
    cudaGetSymbolAddress((void**)&offp,    g_off);
    cudaGetSymbolAddress((void**)&curp,    g_cur);
    cudaGetSymbolAddress((void**)&partp,   g_part);
    cudaGetSymbolAddress((void**)&csrp,    g_csr);
    cudaGetSymbolAddress((void**)&colsump, g_colsum);
    cudaGetSymbolAddress((void**)&gcp,     g_gc);
    cudaGetSymbolAddress((void**)&hp,      g_h);

    const int smem0 = (64  * 144 + 64 * 80 ) * 2 + 8192;
    const int smem1 = (128 * 144 + 64 * 144) * 2 + 8192;
    const int smem2 = (128 * 80  + 64 * 144) * 2 + 8192;
    cudaFuncSetAttribute(gemm_kernel<float, 64, 128, false>, cudaFuncAttributeMaxDynamicSharedMemorySize, smem0);
    cudaFuncSetAttribute(gemm_kernel<__half, 128, 128, true>, cudaFuncAttributeMaxDynamicSharedMemorySize, smem1);
    cudaFuncSetAttribute(gemm_kernel<__half, 128, 64,  true>, cudaFuncAttributeMaxDynamicSharedMemorySize, smem2);

    const int gemm_blocks = (N + 63) / 64;
    const int agg_blocks  = (N + 7) / 8;
    const int scan_blocks = (N + 1023) / 1024;
    const int nb256 = (N + 255) / 256;
    const int eb256 = (E + 255) / 256;

    cudaStream_t s0 = 0;          // captured legacy stream (graph 0)
    cudaStream_t s1 = g_s2;       // forked stream (graph 1)

    zero_all_kernel<<<(2 * N + 255) / 256, 256, 0, s0>>>(degp, hp, colsump, 2 * N);
    cudaEventRecord(g_evFork, s0);
    cudaStreamWaitEvent(s1, g_evFork, 0);

    // ================= graph 0 (s0): GEMM-first phase =================
    {
        const int* src = ei;
        const int* dst = ei + E;
        int*   dg   = degp;
        int*   off  = offp;
        int*   cur  = curp;
        int*   part = partp;
        float* dnv  = dinvp;
        int2*  csr  = csrp;
        float* bC = bufC;
        __half* hX = (__half*)bufB;           // gemm outputs (fp16)
        __half* hG = (__half*)bufA;           // agg outputs (fp16)

        gemm_kernel<float, 64, 128, false><<<gemm_blocks, 256, smem0, s0>>>(x_i, w0, nullptr, hX, N);
        deg_kernel<<<eb256, 256, 0, s0>>>(dst, dg, E);
        scan1_kernel<<<scan_blocks, 1024, 0, s0>>>(dg, off, part, N);
        scan2_kernel<<<1, 128, 0, s0>>>(part, scan_blocks);
        scan3_kernel<<<nb256, 256, 0, s0>>>(off, part, cur, dg, dnv, N);
        scatter_kernel<<<eb256, 256, 0, s0>>>(src, dst, dnv, cur, csr, E);
        agg_csr_kernel<__half, __half, 128><<<agg_blocks, 256, 0, s0>>>(off, csr, hX, dnv, hG, N);
        gemm_kernel<__half, 128, 128, true><<<gemm_blocks, 256, smem1, s0>>>(hG, w1, b0, hX, N);
        agg_csr_kernel<__half, __half, 128><<<agg_blocks, 256, 0, s0>>>(off, csr, hX, dnv, hG, N);
        gemm_kernel<__half, 128, 64, true><<<gemm_blocks, 256, smem2, s0>>>(hG, w2, b1, hX, N);
        agg_csr_kernel<__half, float, 64><<<agg_blocks, 256, 0, s0>>>(off, csr, hX, dnv, bC, N);
        colsum_kernel<<<512, 256, 0, s0>>>(bC, colsump, N);
        gc_kernel<<<1, 64, 0, s0>>>(colsump, b2, att_w, gcp, 1.0f / (float)N);
        attpool_kernel<<<592, 256, 0, s0>>>(bC, b2, gcp, hp, N);
    }

    // ================= graph 1 (s1): CSR + aggregate-first phase ======
    {
        const int* src = ej;
        const int* dst = ej + E;
        int*   dg   = degp + MAXN;
        int*   off  = offp + (MAXN + 1);
        int*   cur  = curp + MAXN;
        int*   part = partp + 256;
        float* dnv  = dinvp + MAXN;
        int2*  csr  = csrp + (size_t)MAXE;
        float* bC = bufC + XCAP;
        __half* hX = (__half*)(bufB + XCAP);  // gemm outputs (fp16)
        __half* hG = (__half*)(bufA + XCAP);  // agg outputs (fp16)

        deg_kernel<<<eb256, 256, 0, s1>>>(dst, dg, E);
        scan1_kernel<<<scan_blocks, 1024, 0, s1>>>(dg, off, part, N);
        scan2_kernel<<<1, 128, 0, s1>>>(part, scan_blocks);
        scan3_kernel<<<nb256, 256, 0, s1>>>(off, part, cur, dg, dnv, N);
        scatter_kernel<<<eb256, 256, 0, s1>>>(src, dst, dnv, cur, csr, E);
        // L0 aggregate-first: x_j fp32 gather (64 cols), fp16 output
        agg_csr_kernel<float, __half, 64><<<agg_blocks, 256, 0, s1>>>(off, csr, x_j, dnv, hG, N);
        gemm_kernel<__half, 64, 128, false><<<gemm_blocks, 256, smem0, s1>>>(hG, w0, nullptr, hX, N);
        gemm_kernel<__half, 128, 128, true><<<gemm_blocks, 256, smem1, s1>>>(hX, w1, b0, hG, N);
        agg_csr_kernel<__half, __half, 128><<<agg_blocks, 256, 0, s1>>>(off, csr, hG, dnv, hX, N);
        gemm_kernel<__half, 128, 64, true><<<gemm_blocks, 256, smem2, s1>>>(hX, w2, b1, hG, N);
        agg_csr_kernel<__half, float, 64><<<agg_blocks, 256, 0, s1>>>(off, csr, hG, dnv, bC, N);
        colsum_kernel<<<512, 256, 0, s1>>>(bC, colsump + 64, N);
        gc_kernel<<<1, 64, 0, s1>>>(colsump + 64, b2, att_w, gcp + 64, 1.0f / (float)N);
        attpool_kernel<<<592, 256, 0, s1>>>(bC, b2, gcp + 64, hp + 64, N);
    }

    cudaEventRecord(g_evJoin, s1);
    cudaStreamWaitEvent(s0, g_evJoin, 0);

    final_kernel<<<1, 1024, 0, s0>>>(hp, ntn_wt, ntn_wm, ntn_b,
                                     mw0, mb0, mw1, mb1, mw2, mb2, mw3, mb3,
                                     sw, sb, out);
}

// round 15
// speedup vs baseline: 1.5923x; 1.0318x over previous
#include <cuda_runtime.h>
#include <cuda_fp16.h>
#include <math.h>
#include <mma.h>

// ---------------------------------------------------------------------------
// SimGNN on GB300: two anti-phased streams; fp16 activations end-to-end
// (fp32 math); fp16 tensor-core GEMMs; 4-edge-unrolled CSR aggregation.
// ---------------------------------------------------------------------------

#define MAXN 100000
#define MAXE 1300000
#define XCAP ((size_t)MAXN * 128)

using namespace nvcuda;

__device__ __align__(16) float g_bufA[2 * XCAP];   // carved: fp16 agg outputs
__device__ __align__(16) float g_bufB[2 * XCAP];   // carved: fp16 gemm outputs
__device__ __align__(16) float g_bufC[2 * XCAP];   // carved: fp16 final agg + x_j fp16
__device__ __align__(16) float g_dinv[2 * MAXN];
__device__ __align__(16) int   g_deg [2 * MAXN];
__device__ __align__(16) int   g_off [2 * (MAXN + 1)];
__device__ __align__(16) int   g_cur [2 * MAXN];
__device__ __align__(16) int   g_part[2 * 256];
__device__ __align__(16) int2  g_csr [2 * (size_t)MAXE];
__device__ __align__(16) float g_colsum[2 * 64];
__device__ __align__(16) float g_gc[2 * 64];
__device__ __align__(16) float g_h[128];

static cudaStream_t g_s2;
static cudaEvent_t  g_evFork, g_evJoin;
namespace {
struct StreamInit {
    StreamInit() {
        cudaStreamCreateWithFlags(&g_s2, cudaStreamNonBlocking);
        cudaEventCreateWithFlags(&g_evFork, cudaEventDisableTiming);
        cudaEventCreateWithFlags(&g_evJoin, cudaEventDisableTiming);
    }
};
static StreamInit s_streamInit;
}

// ------------------------- type-generic loads/stores -----------------------
__device__ __forceinline__ float4 load4(const float* p) { return *(const float4*)p; }
__device__ __forceinline__ float4 load4(const __half* p) {
    const __half2* h = (const __half2*)p;
    float2 a = __half22float2(h[0]);
    float2 b = __half22float2(h[1]);
    return make_float4(a.x, a.y, b.x, b.y);
}
__device__ __forceinline__ float2 load2(const float* p) { return *(const float2*)p; }
__device__ __forceinline__ float2 load2(const __half* p) {
    return __half22float2(*(const __half2*)p);
}
__device__ __forceinline__ float loadS(const float* p) { return *p; }
__device__ __forceinline__ float loadS(const __half* p) { return __half2float(*p); }
__device__ __forceinline__ void store4(float* p, float4 v) { *(float4*)p = v; }
__device__ __forceinline__ void store4(__half* p, float4 v) {
    __half2* h = (__half2*)p;
    h[0] = __floats2half2_rn(v.x, v.y);
    h[1] = __floats2half2_rn(v.z, v.w);
}
__device__ __forceinline__ void store2(float* p, float2 v) { *(float2*)p = v; }
__device__ __forceinline__ void store2(__half* p, float2 v) {
    *(__half2*)p = __floats2half2_rn(v.x, v.y);
}

// ---------------------------------------------------------------------------
__global__ void zero_all_kernel(int* __restrict__ deg, float* __restrict__ h,
                                float* __restrict__ colsum, int n2)
{
    int i = blockIdx.x * blockDim.x + threadIdx.x;
    if (i < n2) deg[i] = 0;
    if (i < 128) { h[i] = 0.f; colsum[i] = 0.f; }
}

// fp32 -> fp16 streaming conversion (n4 = count/4)
__global__ void f2h_kernel(const float* __restrict__ in, __half* __restrict__ out, int n4)
{
    int i = blockIdx.x * blockDim.x + threadIdx.x;
    if (i < n4) {
        float4 v = ((const float4*)in)[i];
        store4(out + i * 4, v);
    }
}

__global__ void deg_kernel(const int* __restrict__ dst, int* __restrict__ deg, int E) {
    int i = blockIdx.x * blockDim.x + threadIdx.x;
    if (i < E) atomicAdd(&deg[dst[i]], 1);
}

// --------------------------- CSR build: scan ------------------------------
__global__ void scan1_kernel(const int* __restrict__ deg, int* __restrict__ off,
                             int* __restrict__ partials, int n)
{
    __shared__ int wsum[32];
    int gid  = blockIdx.x * 1024 + threadIdx.x;
    int lane = threadIdx.x & 31, wid = threadIdx.x >> 5;
    int v = (gid < n) ? deg[gid] : 0;
    int x = v;
#pragma unroll
    for (int o = 1; o < 32; o <<= 1) {
        int y = __shfl_up_sync(0xFFFFFFFFu, x, o);
        if (lane >= o) x += y;
    }
    if (lane == 31) wsum[wid] = x;
    __syncthreads();
    if (wid == 0) {
        int s = wsum[lane];
#pragma unroll
        for (int o = 1; o < 32; o <<= 1) {
            int y = __shfl_up_sync(0xFFFFFFFFu, s, o);
            if (lane >= o) s += y;
        }
        wsum[lane] = s;
    }
    __syncthreads();
    int excl = (wid > 0 ? wsum[wid - 1] : 0) + x - v;
    if (gid < n) off[gid] = excl;
    if (threadIdx.x == 1023) partials[blockIdx.x] = wsum[31];
}

__global__ void scan2_kernel(int* __restrict__ partials, int nb)
{
    __shared__ int wsum[4];
    int t = threadIdx.x;
    int lane = t & 31, w = t >> 5;
    int v = (t < nb) ? partials[t] : 0;
    int x = v;
#pragma unroll
    for (int o = 1; o < 32; o <<= 1) {
        int y = __shfl_up_sync(0xFFFFFFFFu, x, o);
        if (lane >= o) x += y;
    }
    if (lane == 31) wsum[w] = x;
    __syncthreads();
    if (w == 0 && lane < 4) {
        int s = wsum[lane];
#pragma unroll
        for (int o = 1; o < 4; o <<= 1) {
            int y = __shfl_up_sync(0x0000000Fu, s, o);
            if (lane >= o) s += y;
        }
        wsum[lane] = s;
    }
    __syncthreads();
    int incl = x + (w > 0 ? wsum[w - 1] : 0);
    if (t < nb) partials[t] = incl - v;
}

__global__ void scan3_kernel(int* __restrict__ off, const int* __restrict__ partials,
                             int* __restrict__ cur, const int* __restrict__ deg,
                             float* __restrict__ dinv, int n)
{
    int gid = blockIdx.x * blockDim.x + threadIdx.x;
    if (gid < n) {
        int o = off[gid] + partials[gid >> 10];
        off[gid] = o;
        cur[gid] = o;
        if (gid == n - 1) off[n] = o + deg[gid];
        dinv[gid] = rsqrtf((float)(deg[gid] + 1));
    }
}

__global__ void scatter_kernel(const int* __restrict__ src, const int* __restrict__ dst,
                               const float* __restrict__ dinv, int* __restrict__ cur,
                               int2* __restrict__ csr, int E)
{
    int e = blockIdx.x * blockDim.x + threadIdx.x;
    if (e >= E) return;
    int s = src[e], d = dst[e];
    int pos = atomicAdd(&cur[d], 1);
    csr[pos] = make_int2(s, __float_as_int(__ldg(&dinv[s])));
}

// ---------------------------------------------------------------------------
// fp16 tensor-core GEMM (R13-proven): xwH = relu_fused(in) @ W.
template<typename TIN, int DIN, int DOUT, bool FUSE>
__global__ void __launch_bounds__(256)
gemm_kernel(const TIN* __restrict__ in, const float* __restrict__ W,
            const float* __restrict__ bprev, __half* __restrict__ xw, int n)
{
    constexpr int WS = DOUT + 16;
    constexpr int XS = DIN + 16;
    constexpr int CT = DOUT / 16;
    constexpr int NT = CT / 2;

    extern __shared__ __half shh[];
    __half* Ws = shh;
    __half* xs = shh + DIN * WS;
    float*  stage = (float*)(xs + 64 * XS);

    const int tid  = threadIdx.x;
    const int w    = tid >> 5;
    const int lane = tid & 31;

    for (int i = tid; i < DIN * DOUT / 4; i += 256) {
        int row = i / (DOUT / 4), c4 = i % (DOUT / 4);
        float4 v = ((const float4*)(W + row * DOUT))[c4];
        __half2* d = (__half2*)(Ws + row * WS + c4 * 4);
        d[0] = __floats2half2_rn(v.x, v.y);
        d[1] = __floats2half2_rn(v.z, v.w);
    }

    const int row0 = blockIdx.x * 64;
    for (int i = tid; i < 64 * DIN / 4; i += 256) {
        int r = i / (DIN / 4), kk = i % (DIN / 4);
        int row = row0 + r;
        float4 v = make_float4(0.f, 0.f, 0.f, 0.f);
        if (row < n) {
            v = load4(in + (size_t)row * DIN + kk * 4);
            if (FUSE) {
                float4 b = ((const float4*)bprev)[kk];
                v.x = fmaxf(v.x + b.x, 0.f);
                v.y = fmaxf(v.y + b.y, 0.f);
                v.z = fmaxf(v.z + b.z, 0.f);
                v.w = fmaxf(v.w + b.w, 0.f);
            }
        }
        __half2* d = (__half2*)(xs + r * XS + kk * 4);
        d[0] = __floats2half2_rn(v.x, v.y);
        d[1] = __floats2half2_rn(v.z, v.w);
    }
    __syncthreads();

    const int rt  = w >> 1;
    const int ctb = (w & 1) * NT;

    wmma::fragment<wmma::accumulator, 16, 16, 16, float> acc[NT];
#pragma unroll
    for (int t = 0; t < NT; t++) wmma::fill_fragment(acc[t], 0.f);

#pragma unroll
    for (int k0 = 0; k0 < DIN; k0 += 16) {
        wmma::fragment<wmma::matrix_a, 16, 16, 16, __half, wmma::row_major> a;
        wmma::load_matrix_sync(a, xs + rt * 16 * XS + k0, XS);
#pragma unroll
        for (int t = 0; t < NT; t++) {
            wmma::fragment<wmma::matrix_b, 16, 16, 16, __half, wmma::row_major> b;
            wmma::load_matrix_sync(b, Ws + k0 * WS + (ctb + t) * 16, WS);
            wmma::mma_sync(acc[t], a, b, acc[t]);
        }
    }

    const int trow = row0 + rt * 16;
    if (trow < n) {
        float* st = stage + w * 256;
#pragma unroll
        for (int t = 0; t < NT; t++) {
            wmma::store_matrix_sync(st, acc[t], 16, wmma::mem_row_major);
            __syncwarp();
#pragma unroll
            for (int q = 0; q < 4; q++) {
                int idx = lane + q * 32;
                int r = idx >> 3, c = (idx & 7) * 2;
                if (trow + r < n)
                    *(__half2*)(xw + (size_t)(trow + r) * DOUT + (ctb + t) * 16 + c) =
                        __floats2half2_rn(st[r * 16 + c], st[r * 16 + c + 1]);
            }
            __syncwarp();
        }
    }
}

// ---------------------------------------------------------------------------
// CSR aggregation (fp32 accumulate, TIN gather, TOUT store, 4-edge unroll).
template<typename TIN, typename TOUT, int DOUT>
__global__ void agg_csr_kernel(const int* __restrict__ off, const int2* __restrict__ csr,
                               const TIN* __restrict__ xw, const float* __restrict__ dinv,
                               TOUT* __restrict__ aggout, int n)
{
    constexpr int VEC = DOUT / 32;   // 4 or 2
    int node = blockIdx.x * 8 + (threadIdx.x >> 5);
    if (node >= n) return;
    int lane = threadIdx.x & 31;

    float dv = __ldg(&dinv[node]);
    const TIN* xr = xw + (size_t)node * DOUT + lane * VEC;
    float acc[VEC], acc2[VEC];
#pragma unroll
    for (int q = 0; q < VEC; q++) acc2[q] = 0.f;
    if (VEC == 4) {
        float4 v = load4(xr);
        acc[0] = v.x * dv * dv; acc[1] = v.y * dv * dv;
        acc[2] = v.z * dv * dv; acc[3] = v.w * dv * dv;
    } else {
        float2 v = load2(xr);
        acc[0] = v.x * dv * dv; acc[1] = v.y * dv * dv;
    }

    int p = __ldg(&off[node]);
    int pend = __ldg(&off[node + 1]);

    // 4-edge unroll: 4 independent gathers in flight per iteration
    for (; p + 4 <= pend; p += 4) {
        int2 e0 = __ldg(&csr[p]);
        int2 e1 = __ldg(&csr[p + 1]);
        int2 e2 = __ldg(&csr[p + 2]);
        int2 e3 = __ldg(&csr[p + 3]);
        float n0 = __int_as_float(e0.y) * dv;
        float n1 = __int_as_float(e1.y) * dv;
        float n2 = __int_as_float(e2.y) * dv;
        float n3 = __int_as_float(e3.y) * dv;
        const TIN* s0 = xw + (size_t)e0.x * DOUT + lane * VEC;
        const TIN* s1 = xw + (size_t)e1.x * DOUT + lane * VEC;
        const TIN* s2 = xw + (size_t)e2.x * DOUT + lane * VEC;
        const TIN* s3 = xw + (size_t)e3.x * DOUT + lane * VEC;
        if (VEC == 4) {
            float4 v0 = load4(s0), v1 = load4(s1), v2 = load4(s2), v3 = load4(s3);
            acc[0] = fmaf(n0, v0.x, acc[0]);  acc[1] = fmaf(n0, v0.y, acc[1]);
            acc[2] = fmaf(n0, v0.z, acc[2]);  acc[3] = fmaf(n0, v0.w, acc[3]);
            acc2[0] = fmaf(n1, v1.x, acc2[0]); acc2[1] = fmaf(n1, v1.y, acc2[1]);
            acc2[2] = fmaf(n1, v1.z, acc2[2]); acc2[3] = fmaf(n1, v1.w, acc2[3]);
            acc[0] = fmaf(n2, v2.x, acc[0]);  acc[1] = fmaf(n2, v2.y, acc[1]);
            acc[2] = fmaf(n2, v2.z, acc[2]);  acc[3] = fmaf(n2, v2.w, acc[3]);
            acc2[0] = fmaf(n3, v3.x, acc2[0]); acc2[1] = fmaf(n3, v3.y, acc2[1]);
            acc2[2] = fmaf(n3, v3.z, acc2[2]); acc2[3] = fmaf(n3, v3.w, acc2[3]);
        } else {
            float2 v0 = load2(s0), v1 = load2(s1), v2 = load2(s2), v3 = load2(s3);
            acc[0] = fmaf(n0, v0.x, acc[0]);  acc[1] = fmaf(n0, v0.y, acc[1]);
            acc2[0] = fmaf(n1, v1.x, acc2[0]); acc2[1] = fmaf(n1, v1.y, acc2[1]);
            acc[0] = fmaf(n2, v2.x, acc[0]);  acc[1] = fmaf(n2, v2.y, acc[1]);
            acc2[0] = fmaf(n3, v3.x, acc2[0]); acc2[1] = fmaf(n3, v3.y, acc2[1]);
        }
    }
    for (; p < pend; p++) {
        int2 e0 = __ldg(&csr[p]);
        float n0 = __int_as_float(e0.y) * dv;
        const TIN* s0 = xw + (size_t)e0.x * DOUT + lane * VEC;
        if (VEC == 4) {
            float4 v0 = load4(s0);
            acc[0] = fmaf(n0, v0.x, acc[0]); acc[1] = fmaf(n0, v0.y, acc[1]);
            acc[2] = fmaf(n0, v0.z, acc[2]); acc[3] = fmaf(n0, v0.w, acc[3]);
        } else {
            float2 v0 = load2(s0);
            acc[0] = fmaf(n0, v0.x, acc[0]); acc[1] = fmaf(n0, v0.y, acc[1]);
        }
    }

    TOUT* o = aggout + (size_t)node * DOUT + lane * VEC;
    if (VEC == 4)
        store4(o, make_float4(acc[0] + acc2[0], acc[1] + acc2[1],
                              acc[2] + acc2[2], acc[3] + acc2[3]));
    else
        store2(o, make_float2(acc[0] + acc2[0], acc[1] + acc2[1]));
}

// ---------------------------------------------------------------------------
template<typename T>
__global__ void colsum_kernel(const T* __restrict__ agg, float* __restrict__ colsum, int n)
{
    __shared__ float sm[256];
    int c  = threadIdx.x & 63;
    int rl = threadIdx.x >> 6;
    float acc = 0.f;
    for (int row = blockIdx.x * 4 + rl; row < n; row += gridDim.x * 4)
        acc += loadS(agg + (size_t)row * 64 + c);
    sm[threadIdx.x] = acc;
    __syncthreads();
    if (threadIdx.x < 64) {
        float s = sm[c] + sm[64 + c] + sm[128 + c] + sm[192 + c];
        atomicAdd(&colsum[c], s);
    }
}

__global__ void gc_kernel(const float* __restrict__ colsum, const float* __restrict__ b2,
                          const float* __restrict__ Wa, float* __restrict__ gc, float invN)
{
    __shared__ float mean[64];
    int t = threadIdx.x;
    mean[t] = colsum[t] * invN + b2[t];
    __syncthreads();
    float acc = 0.f;
#pragma unroll
    for (int d = 0; d < 64; d++) acc += mean[d] * Wa[d * 64 + t];
    gc[t] = tanhf(acc);
}

template<typename T>
__global__ void attpool_kernel(const T* __restrict__ agg, const float* __restrict__ b2,
                               const float* __restrict__ gc, float* __restrict__ h, int n)
{
    __shared__ float gcs[64], b2s[64];
    __shared__ float red[8][64];
    int tid = threadIdx.x;
    if (tid < 64) { gcs[tid] = gc[tid]; b2s[tid] = b2[tid]; }
    __syncthreads();
    int lane = tid & 31, w = tid >> 5;
    float gx = gcs[2 * lane], gy = gcs[2 * lane + 1];
    float bx = b2s[2 * lane], by = b2s[2 * lane + 1];
    float ax = 0.f, ay = 0.f;
    for (int row = blockIdx.x * 8 + w; row < n; row += gridDim.x * 8) {
        float2 v = load2(agg + (size_t)row * 64 + 2 * lane);
        v.x += bx; v.y += by;
        float d = v.x * gx + v.y * gy;
#pragma unroll
        for (int o = 16; o; o >>= 1) d += __shfl_xor_sync(0xFFFFFFFFu, d, o);
        float att = 1.f / (1.f + expf(-d));
        ax += v.x * att; ay += v.y * att;
    }
    red[w][2 * lane] = ax; red[w][2 * lane + 1] = ay;
    __syncthreads();
    if (w == 0) {
        float sx = 0.f, sy = 0.f;
#pragma unroll
        for (int i = 0; i < 8; i++) { sx += red[i][2 * lane]; sy += red[i][2 * lane + 1]; }
        atomicAdd(&h[2 * lane], sx);
        atomicAdd(&h[2 * lane + 1], sy);
    }
}

// ---------------------------------------------------------------------------
__global__ void final_kernel(const float* __restrict__ h,
                             const float* __restrict__ Wt, const float* __restrict__ Wm,
                             const float* __restrict__ nb,
                             const float* __restrict__ w0, const float* __restrict__ bb0,
                             const float* __restrict__ w1, const float* __restrict__ bb1,
                             const float* __restrict__ w2, const float* __restrict__ bb2,
                             const float* __restrict__ w3, const float* __restrict__ bb3,
                             const float* __restrict__ sw, const float* __restrict__ sb,
                             float* __restrict__ out)
{
    __shared__ float hi[64], hj[64];
    __shared__ float part[1024];
    __shared__ float z[16];
    int t = threadIdx.x;
    if (t < 64) hi[t] = h[t];
    else if (t < 128) hj[t - 64] = h[t];
    __syncthreads();

    int k = t >> 6, e = t & 63;
    const float* wt = Wt + (size_t)k * 4096 + e;
    float acc = 0.f;
#pragma unroll
    for (int d = 0; d < 64; d++) acc += hi[d] * wt[d * 64];
    part[t] = acc * hj[e];
    __syncthreads();

    if (t < 16) {
        float s = 0.f;
        for (int e2 = 0; e2 < 64; e2++) s += part[t * 64 + e2];
        float lin = 0.f;
        const float* wm = Wm + t * 128;
        for (int m = 0; m < 64; m++) lin += wm[m] * hi[m] + wm[64 + m] * hj[m];
        z[t] = tanhf(s + lin + nb[t]);
    }
    __syncthreads();

    if (t == 0) {
        float a[32], b[32];
        for (int j = 0; j < 32; j++) { float s = bb0[j]; for (int i = 0; i < 16; i++) s += z[i] * w0[i * 32 + j]; a[j] = fmaxf(s, 0.f); }
        for (int j = 0; j < 16; j++) { float s = bb1[j]; for (int i = 0; i < 32; i++) s += a[i] * w1[i * 16 + j]; b[j] = fmaxf(s, 0.f); }
        for (int j = 0; j <  8; j++) { float s = bb2[j]; for (int i = 0; i < 16; i++) s += b[i] * w2[i * 8 + j];  a[j] = fmaxf(s, 0.f); }
        for (int j = 0; j <  4; j++) { float s = bb3[j]; for (int i = 0; i <  8; i++) s += a[i] * w3[i * 4 + j];  b[j] = fmaxf(s, 0.f); }
        float s = sb[0];
        for (int i = 0; i < 4; i++) s += b[i] * sw[i];
        out[0] = s;
    }
}

// ---------------------------------------------------------------------------
extern "C" void kernel_launch(void* const* d_in, const int* in_sizes, int n_in,
                              void* d_out, int out_size)
{
    const float* x_i = (const float*)d_in[0];
    const int*   ei  = (const int*)d_in[1];     // int32 (JAX x64 disabled)
    const float* x_j = (const float*)d_in[2];
    const int*   ej  = (const int*)d_in[3];
    const float* w0 = (const float*)d_in[4];
    const float* b0 = (const float*)d_in[5];
    const float* w1 = (const float*)d_in[6];
    const float* b1 = (const float*)d_in[7];
    const float* w2 = (const float*)d_in[8];
    const float* b2 = (const float*)d_in[9];
    const float* att_w  = (const float*)d_in[10];
    const float* ntn_wt = (const float*)d_in[11];
    const float* ntn_wm = (const float*)d_in[12];
    const float* ntn_b  = (const float*)d_in[13];
    const float* mw0 = (const float*)d_in[14];
    const float* mb0 = (const float*)d_in[15];
    const float* mw1 = (const float*)d_in[16];
    const float* mb1 = (const float*)d_in[17];
    const float* mw2 = (const float*)d_in[18];
    const float* mb2 = (const float*)d_in[19];
    const float* mw3 = (const float*)d_in[20];
    const float* mb3 = (const float*)d_in[21];
    const float* sw  = (const float*)d_in[22];
    const float* sb  = (const float*)d_in[23];
    float* out = (float*)d_out;

    const int N = in_sizes[0] / 64;
    const int E = in_sizes[1] / 2;

    float *bufA, *bufB, *bufC, *dinvp, *colsump, *gcp, *hp;
    int *degp, *offp, *curp, *partp;
    int2* csrp;
    cudaGetSymbolAddress((void**)&bufA,    g_bufA);
    cudaGetSymbolAddress((void**)&bufB,    g_bufB);
    cudaGetSymbolAddress((void**)&bufC,    g_bufC);
    cudaGetSymbolAddress((void**)&dinvp,   g_dinv);
    cudaGetSymbolAddress((void**)&degp,    g_deg);
    cudaGetSymbolAddress((void**)&offp,    g_off);
    cudaGetSymbolAddress((void**)&curp,    g_cur);
    cudaGetSymbolAddress((void**)&partp,   g_part);
    cudaGetSymbolAddress((void**)&csrp,    g_csr);
    cudaGetSymbolAddress((void**)&colsump, g_colsum);
    cudaGetSymbolAddress((void**)&gcp,     g_gc);
    cudaGetSymbolAddress((void**)&hp,      g_h);

    const int smem0 = (64  * 144 + 64 * 80 ) * 2 + 8192;
    const int smem1 = (128 * 144 + 64 * 144) * 2 + 8192;
    const int smem2 = (128 * 80  + 64 * 144) * 2 + 8192;
    cudaFuncSetAttribute(gemm_kernel<float, 64, 128, false>, cudaFuncAttributeMaxDynamicSharedMemorySize, smem0);
    cudaFuncSetAttribute(gemm_kernel<__half, 64, 128, false>, cudaFuncAttributeMaxDynamicSharedMemorySize, smem0);
    cudaFuncSetAttribute(gemm_kernel<__half, 128, 128, true>, cudaFuncAttributeMaxDynamicSharedMemorySize, smem1);
    cudaFuncSetAttribute(gemm_kernel<__half, 128, 64,  true>, cudaFuncAttributeMaxDynamicSharedMemorySize, smem2);

    const int gemm_blocks = (N + 63) / 64;
    const int agg_blocks  = (N + 7) / 8;
    const int scan_blocks = (N + 1023) / 1024;
    const int nb256 = (N + 255) / 256;
    const int eb256 = (E + 255) / 256;

    cudaStream_t s0 = 0;
    cudaStream_t s1 = g_s2;

    zero_all_kernel<<<(2 * N + 255) / 256, 256, 0, s0>>>(degp, hp, colsump, 2 * N);
    cudaEventRecord(g_evFork, s0);
    cudaStreamWaitEvent(s1, g_evFork, 0);

    // ================= graph 0 (s0): GEMM-first phase =================
    {
        const int* src = ei;
        const int* dst = ei + E;
        int*   dg   = degp;
        int*   off  = offp;
        int*   cur  = curp;
        int*   part = partp;
        float* dnv  = dinvp;
        int2*  csr  = csrp;
        __half* hX = (__half*)bufB;           // gemm outputs (fp16)
        __half* hG = (__half*)bufA;           // agg outputs (fp16)
        __half* hC = (__half*)bufC;           // final agg (fp16)

        gemm_kernel<float, 64, 128, false><<<gemm_blocks, 256, smem0, s0>>>(x_i, w0, nullptr, hX, N);
        deg_kernel<<<eb256, 256, 0, s0>>>(dst, dg, E);
        scan1_kernel<<<scan_blocks, 1024, 0, s0>>>(dg, off, part, N);
        scan2_kernel<<<1, 128, 0, s0>>>(part, scan_blocks);
        scan3_kernel<<<nb256, 256, 0, s0>>>(off, part, cur, dg, dnv, N);
        scatter_kernel<<<eb256, 256, 0, s0>>>(src, dst, dnv, cur, csr, E);
        agg_csr_kernel<__half, __half, 128><<<agg_blocks, 256, 0, s0>>>(off, csr, hX, dnv, hG, N);
        gemm_kernel<__half, 128, 128, true><<<gemm_blocks, 256, smem1, s0>>>(hG, w1, b0, hX, N);
        agg_csr_kernel<__half, __half, 128><<<agg_blocks, 256, 0, s0>>>(off, csr, hX, dnv, hG, N);
        gemm_kernel<__half, 128, 64, true><<<gemm_blocks, 256, smem2, s0>>>(hG, w2, b1, hX, N);
        agg_csr_kernel<__half, __half, 64><<<agg_blocks, 256, 0, s0>>>(off, csr, hX, dnv, hC, N);
        colsum_kernel<__half><<<512, 256, 0, s0>>>(hC, colsump, N);
        gc_kernel<<<1, 64, 0, s0>>>(colsump, b2, att_w, gcp, 1.0f / (float)N);
        attpool_kernel<__half><<<592, 256, 0, s0>>>(hC, b2, gcp, hp, N);
    }

    // ================= graph 1 (s1): CSR + aggregate-first phase ======
    {
        const int* src = ej;
        const int* dst = ej + E;
        int*   dg   = degp + MAXN;
        int*   off  = offp + (MAXN + 1);
        int*   cur  = curp + MAXN;
        int*   part = partp + 256;
        float* dnv  = dinvp + MAXN;
        int2*  csr  = csrp + (size_t)MAXE;
        __half* hX  = (__half*)(bufB + XCAP);   // gemm outputs (fp16)
        __half* hG  = (__half*)(bufA + XCAP);   // agg outputs (fp16)
        __half* hC  = (__half*)(bufC + XCAP);   // final agg (fp16), N*64 halfs
        __half* hXj = hC + XCAP / 2;            // x_j fp16, N*64 halfs

        // Convert x_j to fp16 (halves L0 gather traffic), then CSR build
        f2h_kernel<<<(N * 64 / 4 + 255) / 256, 256, 0, s1>>>(x_j, hXj, N * 64 / 4);
        deg_kernel<<<eb256, 256, 0, s1>>>(dst, dg, E);
        scan1_kernel<<<scan_blocks, 1024, 0, s1>>>(dg, off, part, N);
        scan2_kernel<<<1, 128, 0, s1>>>(part, scan_blocks);
        scan3_kernel<<<nb256, 256, 0, s1>>>(off, part, cur, dg, dnv, N);
        scatter_kernel<<<eb256, 256, 0, s1>>>(src, dst, dnv, cur, csr, E);
        agg_csr_kernel<__half, __half, 64><<<agg_blocks, 256, 0, s1>>>(off, csr, hXj, dnv, hG, N);
        gemm_kernel<__half, 64, 128, false><<<gemm_blocks, 256, smem0, s1>>>(hG, w0, nullptr, hX, N);
        gemm_kernel<__half, 128, 128, true><<<gemm_blocks, 256, smem1, s1>>>(hX, w1, b0, hG, N);
        agg_csr_kernel<__half, __half, 128><<<agg_blocks, 256, 0, s1>>>(off, csr, hG, dnv, hX, N);
        gemm_kernel<__half, 128, 64, true><<<gemm_blocks, 256, smem2, s1>>>(hX, w2, b1, hG, N);
        agg_csr_kernel<__half, __half, 64><<<agg_blocks, 256, 0, s1>>>(off, csr, hG, dnv, hC, N);
        colsum_kernel<__half><<<512, 256, 0, s1>>>(hC, colsump + 64, N);
        gc_kernel<<<1, 64, 0, s1>>>(colsump + 64, b2, att_w, gcp + 64, 1.0f / (float)N);
        attpool_kernel<__half><<<592, 256, 0, s1>>>(hC, b2, gcp + 64, hp + 64, N);
    }

    cudaEventRecord(g_evJoin, s1);
    cudaStreamWaitEvent(s0, g_evJoin, 0);

    final_kernel<<<1, 1024, 0, s0>>>(hp, ntn_wt, ntn_wm, ntn_b,
                                     mw0, mb0, mw1, mb1, mw2, mb2, mw3, mb3,
                                     sw, sb, out);
}